// round 3
// baseline (speedup 1.0000x reference)
#include <cuda_runtime.h>
#include <math.h>

// Problem constants
#define BATCH 4
#define SEQ   2048
#define DIN   1024
#define DOUT  1024
#define MTOT  (BATCH * SEQ)          // 8192 rows for QKV projection

// Scratch (device globals — no allocation allowed)
__device__ float g_Q[MTOT * DOUT];                 // 32 MB
__device__ float g_K[MTOT * DOUT];                 // 32 MB
__device__ float g_V[MTOT * DOUT];                 // 32 MB
__device__ float g_S[(size_t)BATCH * SEQ * SEQ];   // 64 MB

// ---------------------------------------------------------------------------
// Kernel 1: fused QKV projection.  Q/K/V[m][n] = sum_k x[m][k]*W[k][n] + b[n]
// Tile: 128 (M) x 64 (N) x 16 (K). 256 threads, each computes 8x4 per matrix.
// ---------------------------------------------------------------------------
__global__ __launch_bounds__(256) void qkv_kernel(
    const float* __restrict__ x,
    const float* __restrict__ Wq, const float* __restrict__ bq,
    const float* __restrict__ Wk, const float* __restrict__ bk,
    const float* __restrict__ Wv, const float* __restrict__ bv)
{
    __shared__ float Xs[16][128];
    __shared__ float Wqs[16][64], Wks[16][64], Wvs[16][64];

    const int t  = threadIdx.x;
    const int m0 = blockIdx.y * 128;
    const int n0 = blockIdx.x * 64;
    const int tx = t & 15;        // 16 column groups of 4
    const int ty = t >> 4;        // 16 row groups of 8

    float aq[8][4] = {}, ak[8][4] = {}, av[8][4] = {};

    for (int k0 = 0; k0 < DIN; k0 += 16) {
        // Load X tile (128x16), transposed into Xs[k][m]
        #pragma unroll
        for (int l = 0; l < 2; l++) {
            int idx = t + l * 256;              // 0..511
            int row = idx >> 2;                 // 0..127
            int c4  = idx & 3;                  // 0..3
            float4 v = *(const float4*)&x[(size_t)(m0 + row) * DIN + k0 + c4 * 4];
            Xs[c4 * 4 + 0][row] = v.x;
            Xs[c4 * 4 + 1][row] = v.y;
            Xs[c4 * 4 + 2][row] = v.z;
            Xs[c4 * 4 + 3][row] = v.w;
        }
        // Load W tiles (16x64 each)
        {
            int row = t >> 4;                   // 0..15
            int c4  = t & 15;                   // 0..15
            *(float4*)&Wqs[row][c4 * 4] = *(const float4*)&Wq[(size_t)(k0 + row) * DOUT + n0 + c4 * 4];
            *(float4*)&Wks[row][c4 * 4] = *(const float4*)&Wk[(size_t)(k0 + row) * DOUT + n0 + c4 * 4];
            *(float4*)&Wvs[row][c4 * 4] = *(const float4*)&Wv[(size_t)(k0 + row) * DOUT + n0 + c4 * 4];
        }
        __syncthreads();

        #pragma unroll
        for (int k = 0; k < 16; k++) {
            float a[8];
            *(float4*)&a[0] = *(const float4*)&Xs[k][ty * 8];
            *(float4*)&a[4] = *(const float4*)&Xs[k][ty * 8 + 4];
            float wq[4], wk[4], wv[4];
            *(float4*)&wq[0] = *(const float4*)&Wqs[k][tx * 4];
            *(float4*)&wk[0] = *(const float4*)&Wks[k][tx * 4];
            *(float4*)&wv[0] = *(const float4*)&Wvs[k][tx * 4];
            #pragma unroll
            for (int i = 0; i < 8; i++)
                #pragma unroll
                for (int j = 0; j < 4; j++) {
                    aq[i][j] = fmaf(a[i], wq[j], aq[i][j]);
                    ak[i][j] = fmaf(a[i], wk[j], ak[i][j]);
                    av[i][j] = fmaf(a[i], wv[j], av[i][j]);
                }
        }
        __syncthreads();
    }

    #pragma unroll
    for (int i = 0; i < 8; i++) {
        size_t m = m0 + ty * 8 + i;
        #pragma unroll
        for (int j = 0; j < 4; j++) {
            int n = n0 + tx * 4 + j;
            g_Q[m * DOUT + n] = aq[i][j] + bq[n];
            g_K[m * DOUT + n] = ak[i][j] + bk[n];
            g_V[m * DOUT + n] = av[i][j] + bv[n];
        }
    }
}

// ---------------------------------------------------------------------------
// Kernel 2: scores  S[b][i][j] = scale * dot(Q[b][i], K[b][j]),  mask j>i.
// Tile 128x128x16, 256 threads, 8x8 per thread. Fully-masked tiles fast-path.
// ---------------------------------------------------------------------------
__global__ __launch_bounds__(256) void scores_kernel()
{
    const int b  = blockIdx.z;
    const int it = blockIdx.y;
    const int jt = blockIdx.x;
    const int i0 = it * 128;
    const int j0 = jt * 128;
    const int t  = threadIdx.x;

    float* S = g_S + (size_t)b * SEQ * SEQ;

    if (j0 > i0 + 127) {
        // fully masked tile: write -inf with float4 stores, coalesced
        const float4 ninf4 = make_float4(-INFINITY, -INFINITY, -INFINITY, -INFINITY);
        for (int e = t; e < 128 * 32; e += 256) {
            int r = e >> 5, c = e & 31;
            *(float4*)&S[(size_t)(i0 + r) * SEQ + j0 + c * 4] = ninf4;
        }
        return;
    }

    const float* Q = g_Q + (size_t)b * SEQ * DOUT;
    const float* K = g_K + (size_t)b * SEQ * DOUT;

    __shared__ float Qs[16][128];
    __shared__ float Ks[16][128];

    const int tx = t & 15;
    const int ty = t >> 4;
    float acc[8][8] = {};

    for (int k0 = 0; k0 < DOUT; k0 += 16) {
        #pragma unroll
        for (int l = 0; l < 2; l++) {
            int idx = t + l * 256;
            int row = idx >> 2;
            int c4  = idx & 3;
            float4 q = *(const float4*)&Q[(size_t)(i0 + row) * DOUT + k0 + c4 * 4];
            Qs[c4 * 4 + 0][row] = q.x; Qs[c4 * 4 + 1][row] = q.y;
            Qs[c4 * 4 + 2][row] = q.z; Qs[c4 * 4 + 3][row] = q.w;
            float4 kk = *(const float4*)&K[(size_t)(j0 + row) * DOUT + k0 + c4 * 4];
            Ks[c4 * 4 + 0][row] = kk.x; Ks[c4 * 4 + 1][row] = kk.y;
            Ks[c4 * 4 + 2][row] = kk.z; Ks[c4 * 4 + 3][row] = kk.w;
        }
        __syncthreads();

        #pragma unroll
        for (int k = 0; k < 16; k++) {
            float a[8], bb[8];
            *(float4*)&a[0]  = *(const float4*)&Qs[k][ty * 8];
            *(float4*)&a[4]  = *(const float4*)&Qs[k][ty * 8 + 4];
            *(float4*)&bb[0] = *(const float4*)&Ks[k][tx * 8];
            *(float4*)&bb[4] = *(const float4*)&Ks[k][tx * 8 + 4];
            #pragma unroll
            for (int i = 0; i < 8; i++)
                #pragma unroll
                for (int j = 0; j < 8; j++)
                    acc[i][j] = fmaf(a[i], bb[j], acc[i][j]);
        }
        __syncthreads();
    }

    const float scale = 0.03125f;  // 1/sqrt(1024)
    #pragma unroll
    for (int i = 0; i < 8; i++) {
        int gi = i0 + ty * 8 + i;
        #pragma unroll
        for (int j = 0; j < 8; j++) {
            int gj = j0 + tx * 8 + j;
            float v = (gj > gi) ? -INFINITY : acc[i][j] * scale;
            S[(size_t)gi * SEQ + gj] = v;
        }
    }
}

// ---------------------------------------------------------------------------
// Kernel 3: row softmax over S (row length = SEQ = 2048). One block per row.
// ---------------------------------------------------------------------------
__device__ __forceinline__ float warp_reduce_max(float v) {
    #pragma unroll
    for (int o = 16; o > 0; o >>= 1) v = fmaxf(v, __shfl_xor_sync(0xFFFFFFFFu, v, o));
    return v;
}
__device__ __forceinline__ float warp_reduce_sum(float v) {
    #pragma unroll
    for (int o = 16; o > 0; o >>= 1) v += __shfl_xor_sync(0xFFFFFFFFu, v, o);
    return v;
}

__global__ __launch_bounds__(256) void softmax_kernel()
{
    const size_t row = blockIdx.x;              // 0 .. BATCH*SEQ-1
    float* S = g_S + row * SEQ;
    const int t = threadIdx.x;
    __shared__ float red[8];

    float vals[8];
    float mx = -INFINITY;
    #pragma unroll
    for (int l = 0; l < 8; l++) {
        vals[l] = S[t + l * 256];
        mx = fmaxf(mx, vals[l]);
    }
    mx = warp_reduce_max(mx);
    if ((t & 31) == 0) red[t >> 5] = mx;
    __syncthreads();
    if (t < 8) {
        float v = red[t];
        #pragma unroll
        for (int o = 4; o > 0; o >>= 1) v = fmaxf(v, __shfl_xor_sync(0xFFu, v, o));
        red[t] = v;
    }
    __syncthreads();
    mx = red[0];

    float sum = 0.f;
    #pragma unroll
    for (int l = 0; l < 8; l++) {
        float e = __expf(vals[l] - mx);   // exp(-inf) -> 0 for masked
        vals[l] = e;
        sum += e;
    }
    sum = warp_reduce_sum(sum);
    __syncthreads();
    if ((t & 31) == 0) red[t >> 5] = sum;
    __syncthreads();
    if (t < 8) {
        float v = red[t];
        #pragma unroll
        for (int o = 4; o > 0; o >>= 1) v += __shfl_xor_sync(0xFFu, v, o);
        red[t] = v;
    }
    __syncthreads();
    const float inv = 1.f / red[0];

    #pragma unroll
    for (int l = 0; l < 8; l++)
        S[t + l * 256] = vals[l] * inv;
}

// ---------------------------------------------------------------------------
// Kernel 4: context = P @ V, per batch. Causality: P[i][j]==0 for j>i, so the
// k-loop for row tile it only needs k < (it+1)*128.
// Tile 128x128x16, 8x8 per thread.
// ---------------------------------------------------------------------------
__global__ __launch_bounds__(256) void pv_kernel(float* __restrict__ out)
{
    const int b  = blockIdx.z;
    const int it = blockIdx.y;
    const int dt = blockIdx.x;
    const int i0 = it * 128;
    const int d0 = dt * 128;
    const int t  = threadIdx.x;
    const int tx = t & 15;
    const int ty = t >> 4;

    const float* P = g_S + (size_t)b * SEQ * SEQ;
    const float* V = g_V + (size_t)b * SEQ * DOUT;
    float* C = out + (size_t)b * SEQ * DOUT;

    __shared__ float As[16][128];   // P tile, transposed [k][i]
    __shared__ float Bs[16][128];   // V tile [k][d]

    float acc[8][8] = {};
    const int kend = i0 + 128;      // causal truncation

    for (int k0 = 0; k0 < kend; k0 += 16) {
        #pragma unroll
        for (int l = 0; l < 2; l++) {
            int idx = t + l * 256;
            // P tile: 128 rows x 16 cols, transposed
            int row = idx >> 2;
            int c4  = idx & 3;
            float4 p = *(const float4*)&P[(size_t)(i0 + row) * SEQ + k0 + c4 * 4];
            As[c4 * 4 + 0][row] = p.x; As[c4 * 4 + 1][row] = p.y;
            As[c4 * 4 + 2][row] = p.z; As[c4 * 4 + 3][row] = p.w;
            // V tile: 16 rows x 128 cols, direct
            int vr = idx >> 5;              // 0..15
            int vc = idx & 31;              // 0..31 (x4)
            *(float4*)&Bs[vr][vc * 4] = *(const float4*)&V[(size_t)(k0 + vr) * DOUT + d0 + vc * 4];
        }
        __syncthreads();

        #pragma unroll
        for (int k = 0; k < 16; k++) {
            float a[8], bb[8];
            *(float4*)&a[0]  = *(const float4*)&As[k][ty * 8];
            *(float4*)&a[4]  = *(const float4*)&As[k][ty * 8 + 4];
            *(float4*)&bb[0] = *(const float4*)&Bs[k][tx * 8];
            *(float4*)&bb[4] = *(const float4*)&Bs[k][tx * 8 + 4];
            #pragma unroll
            for (int i = 0; i < 8; i++)
                #pragma unroll
                for (int j = 0; j < 8; j++)
                    acc[i][j] = fmaf(a[i], bb[j], acc[i][j]);
        }
        __syncthreads();
    }

    #pragma unroll
    for (int i = 0; i < 8; i++) {
        size_t gi = i0 + ty * 8 + i;
        #pragma unroll
        for (int j = 0; j < 8; j++)
            C[gi * DOUT + d0 + tx * 8 + j] = acc[i][j];
    }
}

// ---------------------------------------------------------------------------
extern "C" void kernel_launch(void* const* d_in, const int* in_sizes, int n_in,
                              void* d_out, int out_size)
{
    const float* x  = (const float*)d_in[0];
    const float* Wq = (const float*)d_in[1];
    const float* bq = (const float*)d_in[2];
    const float* Wk = (const float*)d_in[3];
    const float* bk = (const float*)d_in[4];
    const float* Wv = (const float*)d_in[5];
    const float* bv = (const float*)d_in[6];
    float* out = (float*)d_out;

    // 1) QKV projection: grid (DOUT/64, MTOT/128)
    qkv_kernel<<<dim3(DOUT / 64, MTOT / 128), 256>>>(x, Wq, bq, Wk, bk, Wv, bv);

    // 2) Scores with causal mask: grid (SEQ/128, SEQ/128, BATCH)
    scores_kernel<<<dim3(SEQ / 128, SEQ / 128, BATCH), 256>>>();

    // 3) Row softmax: one block per row
    softmax_kernel<<<BATCH * SEQ, 256>>>();

    // 4) Context = P @ V: grid (DOUT/128, SEQ/128, BATCH)
    pv_kernel<<<dim3(DOUT / 128, SEQ / 128, BATCH), 256>>>(out);
}

// round 8
// speedup vs baseline: 3.4904x; 3.4904x over previous
#include <cuda_runtime.h>
#include <cuda_bf16.h>
#include <math.h>
#include <stdint.h>

#define BATCH 4
#define SEQ   2048
#define DIN   1024
#define DOUT  1024
#define MTOT  (BATCH*SEQ)            // 8192
#define NCAT  (3*DOUT)               // 3072

// ---------------------------------------------------------------------------
// Scratch (device globals)
// ---------------------------------------------------------------------------
__device__ __nv_bfloat16 g_xh[(size_t)MTOT*DIN];
__device__ __nv_bfloat16 g_xl[(size_t)MTOT*DIN];
__device__ __nv_bfloat16 g_Wth[(size_t)NCAT*DIN];   // W^T concat [n][k]
__device__ __nv_bfloat16 g_Wtl[(size_t)NCAT*DIN];
__device__ float         g_bcat[NCAT];
__device__ __nv_bfloat16 g_Qh[(size_t)MTOT*DOUT];
__device__ __nv_bfloat16 g_Ql[(size_t)MTOT*DOUT];
__device__ __nv_bfloat16 g_Kh[(size_t)MTOT*DOUT];
__device__ __nv_bfloat16 g_Kl[(size_t)MTOT*DOUT];
__device__ float         g_V [(size_t)MTOT*DOUT];
__device__ __nv_bfloat16 g_Vth[(size_t)BATCH*DOUT*SEQ];  // V^T [b][d][j]
__device__ __nv_bfloat16 g_Vtl[(size_t)BATCH*DOUT*SEQ];
__device__ float         g_S [(size_t)BATCH*SEQ*SEQ];
__device__ __nv_bfloat16 g_Ph[(size_t)BATCH*SEQ*SEQ];
__device__ __nv_bfloat16 g_Pl[(size_t)BATCH*SEQ*SEQ];

// ---------------------------------------------------------------------------
// Baseline-PTX tensor helpers (mma.sync + ldmatrix; legal on plain sm_103)
// ---------------------------------------------------------------------------
__device__ __forceinline__ uint32_t smem_u32(const void* p) {
    uint32_t a;
    asm("{ .reg .u64 t; cvta.to.shared.u64 t, %1; cvt.u32.u64 %0, t; }" : "=r"(a) : "l"(p));
    return a;
}
__device__ __forceinline__ void ldsm4(uint32_t* r, uint32_t a) {
    asm volatile("ldmatrix.sync.aligned.m8n8.x4.shared.b16 {%0,%1,%2,%3}, [%4];"
        : "=r"(r[0]), "=r"(r[1]), "=r"(r[2]), "=r"(r[3]) : "r"(a));
}
__device__ __forceinline__ void ldsm2(uint32_t* r, uint32_t a) {
    asm volatile("ldmatrix.sync.aligned.m8n8.x2.shared.b16 {%0,%1}, [%2];"
        : "=r"(r[0]), "=r"(r[1]) : "r"(a));
}
__device__ __forceinline__ void mma_bf16(float* c, const uint32_t* a, const uint32_t* b) {
    asm volatile("mma.sync.aligned.m16n8k16.row.col.f32.bf16.bf16.f32 "
        "{%0,%1,%2,%3}, {%4,%5,%6,%7}, {%8,%9}, {%0,%1,%2,%3};"
        : "+f"(c[0]), "+f"(c[1]), "+f"(c[2]), "+f"(c[3])
        : "r"(a[0]), "r"(a[1]), "r"(a[2]), "r"(a[3]), "r"(b[0]), "r"(b[1]));
}

// hi/lo split
__device__ __forceinline__ void split2(float f, __nv_bfloat16& h, __nv_bfloat16& l) {
    h = __float2bfloat16(f);
    l = __float2bfloat16(f - __bfloat162float(h));
}

// ---------------------------------------------------------------------------
// SMEM layout: per buffer, 4 tiles (Ah, Al, Bh, Bl), each 128 rows x 64 bf16
// padded to stride 72 bf16 (144 B). Tile = 18432 B, buffer = 73728 B, x2.
// ---------------------------------------------------------------------------
#define TSTRIDE_B 144
#define TILE_B    18432
#define BUF_B     73728
#define SMEM_SZ   (2*BUF_B)

// MODE 0: QKV  (A=x split, B=Wt split, N over 3072)
// MODE 1: scores (A=Q split, B=K split, causal tiles only)
// MODE 2: PV   (A=P split, B=Vt split, K truncated)
template<int MODE>
__global__ __launch_bounds__(256) void gemm_kernel(float* __restrict__ out)
{
    extern __shared__ char smem[];
    const uint32_t sb = smem_u32(smem);
    const int t = threadIdx.x;
    const int wid = t >> 5, lane = t & 31;
    const int m_warp = (wid & 1) * 64;
    const int n_warp = (wid >> 1) * 32;

    const __nv_bfloat16 *Ah, *Al, *Bh, *Bl;
    size_t sA, sB;
    int m0, n0, nchunks, b = 0;

    if (MODE == 0) {
        m0 = blockIdx.y * 128; n0 = blockIdx.x * 128;
        Ah = g_xh + (size_t)m0 * DIN;  Al = g_xl + (size_t)m0 * DIN;
        Bh = g_Wth + (size_t)n0 * DIN; Bl = g_Wtl + (size_t)n0 * DIN;
        sA = DIN; sB = DIN; nchunks = DIN / 64;
    } else if (MODE == 1) {
        b = blockIdx.y;
        int x = blockIdx.x, it = 0;
        while ((it + 1) * (it + 2) / 2 <= x) it++;
        int jt = x - it * (it + 1) / 2;
        m0 = it * 128; n0 = jt * 128;
        Ah = g_Qh + ((size_t)b * SEQ + m0) * DOUT; Al = g_Ql + ((size_t)b * SEQ + m0) * DOUT;
        Bh = g_Kh + ((size_t)b * SEQ + n0) * DOUT; Bl = g_Kl + ((size_t)b * SEQ + n0) * DOUT;
        sA = DOUT; sB = DOUT; nchunks = DOUT / 64;
    } else {
        b = blockIdx.z;
        m0 = blockIdx.y * 128; n0 = blockIdx.x * 128;
        Ah = g_Ph + ((size_t)b * SEQ + m0) * SEQ;  Al = g_Pl + ((size_t)b * SEQ + m0) * SEQ;
        Bh = g_Vth + ((size_t)b * DOUT + n0) * SEQ; Bl = g_Vtl + ((size_t)b * DOUT + n0) * SEQ;
        sA = SEQ; sB = SEQ; nchunks = (blockIdx.y + 1) * 2;
    }

    float acc[4][4][4] = {};   // [mt][nt][frag]

    // chunk loader: 4 tiles x (128 rows x 8 float4) = 16 float4 per thread
    auto load_chunk = [&](int buf, int kc) {
        const int k0 = kc * 64;
        #pragma unroll
        for (int l = 0; l < 16; l++) {
            int tile = l >> 2;               // 0:Ah 1:Al 2:Bh 3:Bl
            int e    = (l & 3) * 256 + t;    // 0..1023
            int r    = e >> 3;
            int c8   = e & 7;
            const __nv_bfloat16* src = (tile == 0) ? Ah : (tile == 1) ? Al : (tile == 2) ? Bh : Bl;
            size_t stride = (tile < 2) ? sA : sB;
            float4 v = *(const float4*)(src + (size_t)r * stride + k0 + c8 * 8);
            *(float4*)(smem + buf * BUF_B + tile * TILE_B + r * TSTRIDE_B + c8 * 16) = v;
        }
    };

    load_chunk(0, 0);
    __syncthreads();

    for (int c = 0; c < nchunks; c++) {
        if (c + 1 < nchunks) load_chunk((c + 1) & 1, c + 1);

        const uint32_t base = sb + (c & 1) * BUF_B;
        const int arow = m_warp + (lane & 7) + ((lane >> 3) & 1) * 8;
        const int brow = n_warp + (lane & 7);
        const uint32_t acol = (lane >> 4) * 16;
        const uint32_t bcol = ((lane >> 3) & 1) * 16;

        #pragma unroll
        for (int ks = 0; ks < 4; ks++) {
            const uint32_t kb = ks * 32;     // 16 bf16 = 32 bytes
            uint32_t bh[4][2], bl[4][2];
            #pragma unroll
            for (int nt = 0; nt < 4; nt++) {
                uint32_t addr = base + 2 * TILE_B + (uint32_t)(brow + nt * 8) * TSTRIDE_B + bcol + kb;
                ldsm2(bh[nt], addr);
                ldsm2(bl[nt], addr + TILE_B);
            }
            #pragma unroll
            for (int mt = 0; mt < 4; mt++) {
                uint32_t addr = base + (uint32_t)(arow + mt * 16) * TSTRIDE_B + acol + kb;
                uint32_t ah[4], al[4];
                ldsm4(ah, addr);
                ldsm4(al, addr + TILE_B);
                #pragma unroll
                for (int nt = 0; nt < 4; nt++) {
                    mma_bf16(acc[mt][nt], ah, bh[nt]);
                    mma_bf16(acc[mt][nt], ah, bl[nt]);
                    mma_bf16(acc[mt][nt], al, bh[nt]);
                }
            }
        }
        __syncthreads();
    }

    // ---------------- epilogue straight from registers ----------------
    const int r_loc = m_warp + (lane >> 2);          // local row (of 128), +8 pair
    const int c_loc = n_warp + (lane & 3) * 2;       // local col (of 128)

    #pragma unroll
    for (int mt = 0; mt < 4; mt++) {
        #pragma unroll
        for (int half = 0; half < 2; half++) {
            int r = m0 + r_loc + mt * 16 + half * 8;
            #pragma unroll
            for (int nt = 0; nt < 4; nt++) {
                int cc = n0 + c_loc + nt * 8;
                float v0 = acc[mt][nt][half * 2 + 0];
                float v1 = acc[mt][nt][half * 2 + 1];

                if (MODE == 0) {
                    int mat = n0 >> 10;              // tile-uniform: 0=Q 1=K 2=V
                    int nl = cc & 1023;
                    float f0 = v0 + g_bcat[cc];
                    float f1 = v1 + g_bcat[cc + 1];
                    if (mat == 2) {
                        *(float2*)&g_V[(size_t)r * DOUT + nl] = make_float2(f0, f1);
                    } else {
                        __nv_bfloat16 h0, l0, h1, l1;
                        split2(f0, h0, l0); split2(f1, h1, l1);
                        __nv_bfloat162 hp; hp.x = h0; hp.y = h1;
                        __nv_bfloat162 lp; lp.x = l0; lp.y = l1;
                        __nv_bfloat16* H = (mat == 0) ? g_Qh : g_Kh;
                        __nv_bfloat16* L = (mat == 0) ? g_Ql : g_Kl;
                        *(__nv_bfloat162*)&H[(size_t)r * DOUT + nl] = hp;
                        *(__nv_bfloat162*)&L[(size_t)r * DOUT + nl] = lp;
                    }
                } else if (MODE == 1) {
                    const float scale = 0.03125f;    // 1/sqrt(1024)
                    float f0 = v0 * scale, f1 = v1 * scale;
                    if (m0 == n0) {                  // diagonal tile: mask j>i
                        if (cc     > r) f0 = -INFINITY;
                        if (cc + 1 > r) f1 = -INFINITY;
                    }
                    *(float2*)&g_S[((size_t)b * SEQ + r) * SEQ + cc] = make_float2(f0, f1);
                } else {
                    *(float2*)&out[((size_t)b * SEQ + r) * DOUT + cc] = make_float2(v0, v1);
                }
            }
        }
    }
}

// ---------------------------------------------------------------------------
// Prep kernels
// ---------------------------------------------------------------------------
__global__ __launch_bounds__(256) void prep_x_kernel(const float* __restrict__ x)
{
    size_t i = (size_t)blockIdx.x * 1024 + threadIdx.x * 4;
    float4 v = *(const float4*)&x[i];
    __nv_bfloat16 h, l;
    split2(v.x, h, l); g_xh[i + 0] = h; g_xl[i + 0] = l;
    split2(v.y, h, l); g_xh[i + 1] = h; g_xl[i + 1] = l;
    split2(v.z, h, l); g_xh[i + 2] = h; g_xl[i + 2] = l;
    split2(v.w, h, l); g_xh[i + 3] = h; g_xl[i + 3] = l;
}

__global__ void prep_bias_kernel(const float* __restrict__ bq,
                                 const float* __restrict__ bk,
                                 const float* __restrict__ bv)
{
    int i = blockIdx.x * 256 + threadIdx.x;   // 0..3071
    g_bcat[i] = (i < 1024) ? bq[i] : (i < 2048) ? bk[i - 1024] : bv[i - 2048];
}

// W [k][n] -> Wt [z*1024 + n][k], split
__global__ void prep_wt_kernel(const float* __restrict__ Wq,
                               const float* __restrict__ Wk,
                               const float* __restrict__ Wv)
{
    __shared__ float tl[32][33];
    const int z = blockIdx.z;
    const float* W = (z == 0) ? Wq : (z == 1) ? Wk : Wv;
    int kk = blockIdx.y * 32, nn = blockIdx.x * 32;
    int tx = threadIdx.x, ty = threadIdx.y;
    #pragma unroll
    for (int i = 0; i < 4; i++)
        tl[ty + i * 8][tx] = W[(size_t)(kk + ty + i * 8) * DOUT + nn + tx];
    __syncthreads();
    #pragma unroll
    for (int i = 0; i < 4; i++) {
        float f = tl[tx][ty + i * 8];        // = W[kk+tx][nn+ty+i*8]
        size_t row = (size_t)z * 1024 + nn + ty + i * 8;
        __nv_bfloat16 h, l; split2(f, h, l);
        g_Wth[row * DIN + kk + tx] = h;
        g_Wtl[row * DIN + kk + tx] = l;
    }
}

// V [b][j][d] -> Vt [b][d][j], split
__global__ void vtrans_kernel()
{
    __shared__ float tl[32][33];
    const int bz = blockIdx.z;
    int jj = blockIdx.x * 32, dd = blockIdx.y * 32;
    int tx = threadIdx.x, ty = threadIdx.y;
    #pragma unroll
    for (int i = 0; i < 4; i++)
        tl[ty + i * 8][tx] = g_V[((size_t)bz * SEQ + jj + ty + i * 8) * DOUT + dd + tx];
    __syncthreads();
    #pragma unroll
    for (int i = 0; i < 4; i++) {
        float f = tl[tx][ty + i * 8];        // = V[jj+tx][dd+ty+i*8]
        size_t row = (size_t)bz * DOUT + dd + ty + i * 8;
        __nv_bfloat16 h, l; split2(f, h, l);
        g_Vth[row * SEQ + jj + tx] = h;
        g_Vtl[row * SEQ + jj + tx] = l;
    }
}

// ---------------------------------------------------------------------------
// Softmax + P split; writes only the causally live region (j < row_end)
// ---------------------------------------------------------------------------
__device__ __forceinline__ float wr_max(float v) {
    #pragma unroll
    for (int o = 16; o > 0; o >>= 1) v = fmaxf(v, __shfl_xor_sync(0xFFFFFFFFu, v, o));
    return v;
}
__device__ __forceinline__ float wr_sum(float v) {
    #pragma unroll
    for (int o = 16; o > 0; o >>= 1) v += __shfl_xor_sync(0xFFFFFFFFu, v, o);
    return v;
}

__global__ __launch_bounds__(256) void softmax_split_kernel()
{
    const size_t row = blockIdx.x;          // b*SEQ + i
    const int i_in_b = (int)(row & (SEQ - 1));
    const int row_end = ((i_in_b >> 7) + 1) << 7;   // written (tile) region
    const float* Srow = g_S + row * SEQ;
    const int t = threadIdx.x;
    __shared__ float red[8];

    float vals[8];
    float mx = -INFINITY;
    #pragma unroll
    for (int l = 0; l < 8; l++) {
        int j = t + l * 256;
        vals[l] = (j < row_end) ? Srow[j] : -INFINITY;
        mx = fmaxf(mx, vals[l]);
    }
    mx = wr_max(mx);
    if ((t & 31) == 0) red[t >> 5] = mx;
    __syncthreads();
    if (t < 8) {
        float v = red[t];
        #pragma unroll
        for (int o = 4; o > 0; o >>= 1) v = fmaxf(v, __shfl_xor_sync(0xFFu, v, o));
        red[t] = v;
    }
    __syncthreads();
    mx = red[0];

    float sum = 0.f;
    #pragma unroll
    for (int l = 0; l < 8; l++) {
        float e = (vals[l] == -INFINITY) ? 0.f : __expf(vals[l] - mx);
        vals[l] = e;
        sum += e;
    }
    sum = wr_sum(sum);
    __syncthreads();
    if ((t & 31) == 0) red[t >> 5] = sum;
    __syncthreads();
    if (t < 8) {
        float v = red[t];
        #pragma unroll
        for (int o = 4; o > 0; o >>= 1) v += __shfl_xor_sync(0xFFu, v, o);
        red[t] = v;
    }
    __syncthreads();
    const float inv = 1.f / red[0];

    #pragma unroll
    for (int l = 0; l < 8; l++) {
        int j = t + l * 256;
        if (j < row_end) {
            float p = vals[l] * inv;
            __nv_bfloat16 h, lo; split2(p, h, lo);
            g_Ph[row * SEQ + j] = h;
            g_Pl[row * SEQ + j] = lo;
        }
    }
}

// ---------------------------------------------------------------------------
extern "C" void kernel_launch(void* const* d_in, const int* in_sizes, int n_in,
                              void* d_out, int out_size)
{
    const float* x  = (const float*)d_in[0];
    const float* Wq = (const float*)d_in[1];
    const float* bq = (const float*)d_in[2];
    const float* Wk = (const float*)d_in[3];
    const float* bk = (const float*)d_in[4];
    const float* Wv = (const float*)d_in[5];
    const float* bv = (const float*)d_in[6];
    float* out = (float*)d_out;

    cudaFuncSetAttribute(gemm_kernel<0>, cudaFuncAttributeMaxDynamicSharedMemorySize, SMEM_SZ);
    cudaFuncSetAttribute(gemm_kernel<1>, cudaFuncAttributeMaxDynamicSharedMemorySize, SMEM_SZ);
    cudaFuncSetAttribute(gemm_kernel<2>, cudaFuncAttributeMaxDynamicSharedMemorySize, SMEM_SZ);

    prep_x_kernel<<<MTOT * DIN / 1024, 256>>>(x);
    prep_bias_kernel<<<NCAT / 256, 256>>>(bq, bk, bv);
    prep_wt_kernel<<<dim3(DOUT / 32, DIN / 32, 3), dim3(32, 8)>>>(Wq, Wk, Wv);

    // QKV: N = 3072 concat, M = 8192
    gemm_kernel<0><<<dim3(NCAT / 128, MTOT / 128), 256, SMEM_SZ>>>(out);

    vtrans_kernel<<<dim3(SEQ / 32, DOUT / 32, BATCH), dim3(32, 8)>>>();

    // Scores: lower-triangular tiles only (16*17/2 = 136 per batch)
    gemm_kernel<1><<<dim3(136, BATCH), 256, SMEM_SZ>>>(out);

    softmax_split_kernel<<<BATCH * SEQ, 256>>>();

    // PV: K truncated by causality inside kernel
    gemm_kernel<2><<<dim3(DOUT / 128, SEQ / 128, BATCH), 256, SMEM_SZ>>>(out);
}

// round 9
// speedup vs baseline: 4.2516x; 1.2181x over previous
#include <cuda_runtime.h>
#include <cuda_bf16.h>
#include <math.h>
#include <stdint.h>

#define BATCH 4
#define SEQ   2048
#define DIN   1024
#define DOUT  1024
#define MTOT  (BATCH*SEQ)            // 8192
#define NCAT  (3*DOUT)               // 3072

// ---------------------------------------------------------------------------
// Scratch (device globals)
// ---------------------------------------------------------------------------
__device__ __nv_bfloat16 g_xh[(size_t)MTOT*DIN];
__device__ __nv_bfloat16 g_xl[(size_t)MTOT*DIN];
__device__ __nv_bfloat16 g_Wth[(size_t)NCAT*DIN];   // W^T concat [n][k]
__device__ __nv_bfloat16 g_Wtl[(size_t)NCAT*DIN];
__device__ float         g_bcat[NCAT];
__device__ __nv_bfloat16 g_Qh[(size_t)MTOT*DOUT];
__device__ __nv_bfloat16 g_Ql[(size_t)MTOT*DOUT];
__device__ __nv_bfloat16 g_Kh[(size_t)MTOT*DOUT];
__device__ __nv_bfloat16 g_Kl[(size_t)MTOT*DOUT];
__device__ float         g_V [(size_t)MTOT*DOUT];
__device__ __nv_bfloat16 g_Vth[(size_t)BATCH*DOUT*SEQ];  // V^T [b][d][j]
__device__ __nv_bfloat16 g_Vtl[(size_t)BATCH*DOUT*SEQ];
__device__ float         g_S [(size_t)BATCH*SEQ*SEQ];
__device__ __nv_bfloat16 g_Ph[(size_t)BATCH*SEQ*SEQ];
__device__ __nv_bfloat16 g_Pl[(size_t)BATCH*SEQ*SEQ];

// ---------------------------------------------------------------------------
// Baseline-PTX tensor helpers (mma.sync + ldmatrix + cp.async; plain sm_103)
// ---------------------------------------------------------------------------
__device__ __forceinline__ uint32_t smem_u32(const void* p) {
    uint32_t a;
    asm("{ .reg .u64 t; cvta.to.shared.u64 t, %1; cvt.u32.u64 %0, t; }" : "=r"(a) : "l"(p));
    return a;
}
__device__ __forceinline__ void ldsm4(uint32_t* r, uint32_t a) {
    asm volatile("ldmatrix.sync.aligned.m8n8.x4.shared.b16 {%0,%1,%2,%3}, [%4];"
        : "=r"(r[0]), "=r"(r[1]), "=r"(r[2]), "=r"(r[3]) : "r"(a));
}
__device__ __forceinline__ void ldsm2(uint32_t* r, uint32_t a) {
    asm volatile("ldmatrix.sync.aligned.m8n8.x2.shared.b16 {%0,%1}, [%2];"
        : "=r"(r[0]), "=r"(r[1]) : "r"(a));
}
__device__ __forceinline__ void mma_bf16(float* c, const uint32_t* a, const uint32_t* b) {
    asm volatile("mma.sync.aligned.m16n8k16.row.col.f32.bf16.bf16.f32 "
        "{%0,%1,%2,%3}, {%4,%5,%6,%7}, {%8,%9}, {%0,%1,%2,%3};"
        : "+f"(c[0]), "+f"(c[1]), "+f"(c[2]), "+f"(c[3])
        : "r"(a[0]), "r"(a[1]), "r"(a[2]), "r"(a[3]), "r"(b[0]), "r"(b[1]));
}
__device__ __forceinline__ void cp16(uint32_t saddr, const void* g) {
    asm volatile("cp.async.cg.shared.global [%0], [%1], 16;" :: "r"(saddr), "l"(g));
}
#define CP_COMMIT() asm volatile("cp.async.commit_group;" ::: "memory")
#define CP_WAIT(n)  asm volatile("cp.async.wait_group %0;" :: "n"(n) : "memory")

// hi/lo split
__device__ __forceinline__ void split2(float f, __nv_bfloat16& h, __nv_bfloat16& l) {
    h = __float2bfloat16(f);
    l = __float2bfloat16(f - __bfloat162float(h));
}

// ---------------------------------------------------------------------------
// SMEM layout: per buffer, 4 tiles (Ah, Al, Bh, Bl), each 128 rows x 64 bf16
// padded to stride 72 bf16 (144 B). Tile = 18432 B, buffer = 73728 B, x2.
// ---------------------------------------------------------------------------
#define TSTRIDE_B 144
#define TILE_B    18432
#define BUF_B     73728
#define SMEM_SZ   (2*BUF_B)

// MODE 0: QKV  (A=x split, B=Wt split, N over 3072)
// MODE 1: scores (A=Q split, B=K split, causal tiles only)
// MODE 2: PV   (A=P split, B=Vt split, K truncated)
template<int MODE>
__global__ __launch_bounds__(256) void gemm_kernel(float* __restrict__ out)
{
    extern __shared__ char smem[];
    const uint32_t sb = smem_u32(smem);
    const int t = threadIdx.x;
    const int wid = t >> 5, lane = t & 31;
    const int m_warp = (wid & 1) * 64;
    const int n_warp = (wid >> 1) * 32;

    const __nv_bfloat16 *Ah, *Al, *Bh, *Bl;
    size_t sA, sB;
    int m0, n0, nchunks, b = 0;

    if (MODE == 0) {
        m0 = blockIdx.y * 128; n0 = blockIdx.x * 128;
        Ah = g_xh + (size_t)m0 * DIN;  Al = g_xl + (size_t)m0 * DIN;
        Bh = g_Wth + (size_t)n0 * DIN; Bl = g_Wtl + (size_t)n0 * DIN;
        sA = DIN; sB = DIN; nchunks = DIN / 64;
    } else if (MODE == 1) {
        b = blockIdx.y;
        int x = blockIdx.x, it = 0;
        while ((it + 1) * (it + 2) / 2 <= x) it++;
        int jt = x - it * (it + 1) / 2;
        m0 = it * 128; n0 = jt * 128;
        Ah = g_Qh + ((size_t)b * SEQ + m0) * DOUT; Al = g_Ql + ((size_t)b * SEQ + m0) * DOUT;
        Bh = g_Kh + ((size_t)b * SEQ + n0) * DOUT; Bl = g_Kl + ((size_t)b * SEQ + n0) * DOUT;
        sA = DOUT; sB = DOUT; nchunks = DOUT / 64;
    } else {
        b = blockIdx.z;
        m0 = blockIdx.y * 128; n0 = blockIdx.x * 128;
        Ah = g_Ph + ((size_t)b * SEQ + m0) * SEQ;  Al = g_Pl + ((size_t)b * SEQ + m0) * SEQ;
        Bh = g_Vth + ((size_t)b * DOUT + n0) * SEQ; Bl = g_Vtl + ((size_t)b * DOUT + n0) * SEQ;
        sA = SEQ; sB = SEQ; nchunks = (blockIdx.y + 1) * 2;   // >= 2 always
    }

    float acc[4][4][4] = {};   // [mt][nt][frag]

    // async chunk loader: 4 tiles x (128 rows x 8 x 16B) = 16 cp.async/thread
    auto issue_chunk = [&](int buf, int kc) {
        const int k0 = kc * 64;
        #pragma unroll
        for (int l = 0; l < 16; l++) {
            int tile = l >> 2;               // 0:Ah 1:Al 2:Bh 3:Bl
            int e    = (l & 3) * 256 + t;    // 0..1023
            int r    = e >> 3;
            int c8   = e & 7;
            const __nv_bfloat16* src = (tile == 0) ? Ah : (tile == 1) ? Al : (tile == 2) ? Bh : Bl;
            size_t stride = (tile < 2) ? sA : sB;
            cp16(sb + buf * BUF_B + tile * TILE_B + (uint32_t)(r * TSTRIDE_B + c8 * 16),
                 src + (size_t)r * stride + k0 + c8 * 8);
        }
        CP_COMMIT();
    };

    // prefetch distance 2 (nchunks >= 2 in every mode)
    issue_chunk(0, 0);
    issue_chunk(1, 1);

    for (int c = 0; c < nchunks; c++) {
        if (c + 1 < nchunks) { CP_WAIT(1); } else { CP_WAIT(0); }
        __syncthreads();                     // chunk c resident & visible to all

        const uint32_t base = sb + (c & 1) * BUF_B;
        const int arow = m_warp + (lane & 7) + ((lane >> 3) & 1) * 8;
        const int brow = n_warp + (lane & 7);
        const uint32_t acol = (lane >> 4) * 16;
        const uint32_t bcol = ((lane >> 3) & 1) * 16;

        #pragma unroll
        for (int ks = 0; ks < 4; ks++) {
            const uint32_t kb = ks * 32;     // 16 bf16 = 32 bytes
            uint32_t bh[4][2], bl[4][2];
            #pragma unroll
            for (int nt = 0; nt < 4; nt++) {
                uint32_t addr = base + 2 * TILE_B + (uint32_t)(brow + nt * 8) * TSTRIDE_B + bcol + kb;
                ldsm2(bh[nt], addr);
                ldsm2(bl[nt], addr + TILE_B);
            }
            #pragma unroll
            for (int mt = 0; mt < 4; mt++) {
                uint32_t addr = base + (uint32_t)(arow + mt * 16) * TSTRIDE_B + acol + kb;
                uint32_t ah[4], al[4];
                ldsm4(ah, addr);
                ldsm4(al, addr + TILE_B);
                #pragma unroll
                for (int nt = 0; nt < 4; nt++) {
                    mma_bf16(acc[mt][nt], ah, bh[nt]);
                    mma_bf16(acc[mt][nt], ah, bl[nt]);
                    mma_bf16(acc[mt][nt], al, bh[nt]);
                }
            }
        }
        __syncthreads();                     // all readers done with buf (c&1)
        if (c + 2 < nchunks) issue_chunk(c & 1, c + 2);
    }

    // ---------------- epilogue straight from registers ----------------
    const int r_loc = m_warp + (lane >> 2);          // local row (of 128), +8 pair
    const int c_loc = n_warp + (lane & 3) * 2;       // local col (of 128)

    #pragma unroll
    for (int mt = 0; mt < 4; mt++) {
        #pragma unroll
        for (int half = 0; half < 2; half++) {
            int r = m0 + r_loc + mt * 16 + half * 8;
            #pragma unroll
            for (int nt = 0; nt < 4; nt++) {
                int cc = n0 + c_loc + nt * 8;
                float v0 = acc[mt][nt][half * 2 + 0];
                float v1 = acc[mt][nt][half * 2 + 1];

                if (MODE == 0) {
                    int mat = n0 >> 10;              // tile-uniform: 0=Q 1=K 2=V
                    int nl = cc & 1023;
                    float f0 = v0 + g_bcat[cc];
                    float f1 = v1 + g_bcat[cc + 1];
                    if (mat == 2) {
                        *(float2*)&g_V[(size_t)r * DOUT + nl] = make_float2(f0, f1);
                    } else {
                        __nv_bfloat16 h0, l0, h1, l1;
                        split2(f0, h0, l0); split2(f1, h1, l1);
                        __nv_bfloat162 hp; hp.x = h0; hp.y = h1;
                        __nv_bfloat162 lp; lp.x = l0; lp.y = l1;
                        __nv_bfloat16* H = (mat == 0) ? g_Qh : g_Kh;
                        __nv_bfloat16* L = (mat == 0) ? g_Ql : g_Kl;
                        *(__nv_bfloat162*)&H[(size_t)r * DOUT + nl] = hp;
                        *(__nv_bfloat162*)&L[(size_t)r * DOUT + nl] = lp;
                    }
                } else if (MODE == 1) {
                    const float scale = 0.03125f;    // 1/sqrt(1024)
                    float f0 = v0 * scale, f1 = v1 * scale;
                    if (m0 == n0) {                  // diagonal tile: mask j>i
                        if (cc     > r) f0 = -INFINITY;
                        if (cc + 1 > r) f1 = -INFINITY;
                    }
                    *(float2*)&g_S[((size_t)b * SEQ + r) * SEQ + cc] = make_float2(f0, f1);
                } else {
                    *(float2*)&out[((size_t)b * SEQ + r) * DOUT + cc] = make_float2(v0, v1);
                }
            }
        }
    }
}

// ---------------------------------------------------------------------------
// Prep kernels
// ---------------------------------------------------------------------------
__global__ __launch_bounds__(256) void prep_x_kernel(const float* __restrict__ x)
{
    size_t i = (size_t)blockIdx.x * 1024 + threadIdx.x * 4;
    float4 v = *(const float4*)&x[i];
    __nv_bfloat16 h, l;
    split2(v.x, h, l); g_xh[i + 0] = h; g_xl[i + 0] = l;
    split2(v.y, h, l); g_xh[i + 1] = h; g_xl[i + 1] = l;
    split2(v.z, h, l); g_xh[i + 2] = h; g_xl[i + 2] = l;
    split2(v.w, h, l); g_xh[i + 3] = h; g_xl[i + 3] = l;
}

__global__ void prep_bias_kernel(const float* __restrict__ bq,
                                 const float* __restrict__ bk,
                                 const float* __restrict__ bv)
{
    int i = blockIdx.x * 256 + threadIdx.x;   // 0..3071
    g_bcat[i] = (i < 1024) ? bq[i] : (i < 2048) ? bk[i - 1024] : bv[i - 2048];
}

// W [k][n] -> Wt [z*1024 + n][k], split
__global__ void prep_wt_kernel(const float* __restrict__ Wq,
                               const float* __restrict__ Wk,
                               const float* __restrict__ Wv)
{
    __shared__ float tl[32][33];
    const int z = blockIdx.z;
    const float* W = (z == 0) ? Wq : (z == 1) ? Wk : Wv;
    int kk = blockIdx.y * 32, nn = blockIdx.x * 32;
    int tx = threadIdx.x, ty = threadIdx.y;
    #pragma unroll
    for (int i = 0; i < 4; i++)
        tl[ty + i * 8][tx] = W[(size_t)(kk + ty + i * 8) * DOUT + nn + tx];
    __syncthreads();
    #pragma unroll
    for (int i = 0; i < 4; i++) {
        float f = tl[tx][ty + i * 8];        // = W[kk+tx][nn+ty+i*8]
        size_t row = (size_t)z * 1024 + nn + ty + i * 8;
        __nv_bfloat16 h, l; split2(f, h, l);
        g_Wth[row * DIN + kk + tx] = h;
        g_Wtl[row * DIN + kk + tx] = l;
    }
}

// V [b][j][d] -> Vt [b][d][j], split
__global__ void vtrans_kernel()
{
    __shared__ float tl[32][33];
    const int bz = blockIdx.z;
    int jj = blockIdx.x * 32, dd = blockIdx.y * 32;
    int tx = threadIdx.x, ty = threadIdx.y;
    #pragma unroll
    for (int i = 0; i < 4; i++)
        tl[ty + i * 8][tx] = g_V[((size_t)bz * SEQ + jj + ty + i * 8) * DOUT + dd + tx];
    __syncthreads();
    #pragma unroll
    for (int i = 0; i < 4; i++) {
        float f = tl[tx][ty + i * 8];        // = V[jj+tx][dd+ty+i*8]
        size_t row = (size_t)bz * DOUT + dd + ty + i * 8;
        __nv_bfloat16 h, l; split2(f, h, l);
        g_Vth[row * SEQ + jj + tx] = h;
        g_Vtl[row * SEQ + jj + tx] = l;
    }
}

// ---------------------------------------------------------------------------
// Softmax + P split; writes only the causally live region (j < row_end)
// ---------------------------------------------------------------------------
__device__ __forceinline__ float wr_max(float v) {
    #pragma unroll
    for (int o = 16; o > 0; o >>= 1) v = fmaxf(v, __shfl_xor_sync(0xFFFFFFFFu, v, o));
    return v;
}
__device__ __forceinline__ float wr_sum(float v) {
    #pragma unroll
    for (int o = 16; o > 0; o >>= 1) v += __shfl_xor_sync(0xFFFFFFFFu, v, o);
    return v;
}

__global__ __launch_bounds__(256) void softmax_split_kernel()
{
    const size_t row = blockIdx.x;          // b*SEQ + i
    const int i_in_b = (int)(row & (SEQ - 1));
    const int row_end = ((i_in_b >> 7) + 1) << 7;   // written (tile) region
    const float* Srow = g_S + row * SEQ;
    const int t = threadIdx.x;
    __shared__ float red[8];

    float vals[8];
    float mx = -INFINITY;
    #pragma unroll
    for (int l = 0; l < 8; l++) {
        int j = t + l * 256;
        vals[l] = (j < row_end) ? Srow[j] : -INFINITY;
        mx = fmaxf(mx, vals[l]);
    }
    mx = wr_max(mx);
    if ((t & 31) == 0) red[t >> 5] = mx;
    __syncthreads();
    if (t < 8) {
        float v = red[t];
        #pragma unroll
        for (int o = 4; o > 0; o >>= 1) v = fmaxf(v, __shfl_xor_sync(0xFFu, v, o));
        red[t] = v;
    }
    __syncthreads();
    mx = red[0];

    float sum = 0.f;
    #pragma unroll
    for (int l = 0; l < 8; l++) {
        float e = (vals[l] == -INFINITY) ? 0.f : __expf(vals[l] - mx);
        vals[l] = e;
        sum += e;
    }
    sum = wr_sum(sum);
    __syncthreads();
    if ((t & 31) == 0) red[t >> 5] = sum;
    __syncthreads();
    if (t < 8) {
        float v = red[t];
        #pragma unroll
        for (int o = 4; o > 0; o >>= 1) v += __shfl_xor_sync(0xFFu, v, o);
        red[t] = v;
    }
    __syncthreads();
    const float inv = 1.f / red[0];

    #pragma unroll
    for (int l = 0; l < 8; l++) {
        int j = t + l * 256;
        if (j < row_end) {
            float p = vals[l] * inv;
            __nv_bfloat16 h, lo; split2(p, h, lo);
            g_Ph[row * SEQ + j] = h;
            g_Pl[row * SEQ + j] = lo;
        }
    }
}

// ---------------------------------------------------------------------------
extern "C" void kernel_launch(void* const* d_in, const int* in_sizes, int n_in,
                              void* d_out, int out_size)
{
    const float* x  = (const float*)d_in[0];
    const float* Wq = (const float*)d_in[1];
    const float* bq = (const float*)d_in[2];
    const float* Wk = (const float*)d_in[3];
    const float* bk = (const float*)d_in[4];
    const float* Wv = (const float*)d_in[5];
    const float* bv = (const float*)d_in[6];
    float* out = (float*)d_out;

    cudaFuncSetAttribute(gemm_kernel<0>, cudaFuncAttributeMaxDynamicSharedMemorySize, SMEM_SZ);
    cudaFuncSetAttribute(gemm_kernel<1>, cudaFuncAttributeMaxDynamicSharedMemorySize, SMEM_SZ);
    cudaFuncSetAttribute(gemm_kernel<2>, cudaFuncAttributeMaxDynamicSharedMemorySize, SMEM_SZ);

    prep_x_kernel<<<MTOT * DIN / 1024, 256>>>(x);
    prep_bias_kernel<<<NCAT / 256, 256>>>(bq, bk, bv);
    prep_wt_kernel<<<dim3(DOUT / 32, DIN / 32, 3), dim3(32, 8)>>>(Wq, Wk, Wv);

    // QKV: N = 3072 concat, M = 8192
    gemm_kernel<0><<<dim3(NCAT / 128, MTOT / 128), 256, SMEM_SZ>>>(out);

    vtrans_kernel<<<dim3(SEQ / 32, DOUT / 32, BATCH), dim3(32, 8)>>>();

    // Scores: lower-triangular tiles only (16*17/2 = 136 per batch)
    gemm_kernel<1><<<dim3(136, BATCH), 256, SMEM_SZ>>>(out);

    softmax_split_kernel<<<BATCH * SEQ, 256>>>();

    // PV: K truncated by causality inside kernel
    gemm_kernel<2><<<dim3(DOUT / 128, SEQ / 128, BATCH), 256, SMEM_SZ>>>(out);
}

// round 11
// speedup vs baseline: 4.3111x; 1.0140x over previous
#include <cuda_runtime.h>
#include <cuda_bf16.h>
#include <math.h>
#include <stdint.h>

#define BATCH 4
#define SEQ   2048
#define DIN   1024
#define DOUT  1024
#define MTOT  (BATCH*SEQ)            // 8192
#define NCAT  (3*DOUT)               // 3072

// ---------------------------------------------------------------------------
// Scratch (device globals)
// ---------------------------------------------------------------------------
__device__ __nv_bfloat16 g_xh[(size_t)MTOT*DIN];
__device__ __nv_bfloat16 g_xl[(size_t)MTOT*DIN];
__device__ __nv_bfloat16 g_Wth[(size_t)NCAT*DIN];   // W^T concat [n][k]
__device__ __nv_bfloat16 g_Wtl[(size_t)NCAT*DIN];
__device__ float         g_bcat[NCAT];
__device__ __nv_bfloat16 g_Qh[(size_t)MTOT*DOUT];
__device__ __nv_bfloat16 g_Ql[(size_t)MTOT*DOUT];
__device__ __nv_bfloat16 g_Kh[(size_t)MTOT*DOUT];
__device__ __nv_bfloat16 g_Kl[(size_t)MTOT*DOUT];
__device__ float         g_V [(size_t)MTOT*DOUT];
__device__ __nv_bfloat16 g_Vth[(size_t)BATCH*DOUT*SEQ];  // V^T [b][d][j]
__device__ __nv_bfloat16 g_Vtl[(size_t)BATCH*DOUT*SEQ];
__device__ float         g_S [(size_t)BATCH*SEQ*SEQ];
__device__ __nv_bfloat16 g_Ph[(size_t)BATCH*SEQ*SEQ];
__device__ __nv_bfloat16 g_Pl[(size_t)BATCH*SEQ*SEQ];

// ---------------------------------------------------------------------------
// Baseline-PTX tensor helpers (mma.sync + ldmatrix + cp.async; plain sm_103)
// ---------------------------------------------------------------------------
__device__ __forceinline__ uint32_t smem_u32(const void* p) {
    uint32_t a;
    asm("{ .reg .u64 t; cvta.to.shared.u64 t, %1; cvt.u32.u64 %0, t; }" : "=r"(a) : "l"(p));
    return a;
}
__device__ __forceinline__ void ldsm4(uint32_t* r, uint32_t a) {
    asm volatile("ldmatrix.sync.aligned.m8n8.x4.shared.b16 {%0,%1,%2,%3}, [%4];"
        : "=r"(r[0]), "=r"(r[1]), "=r"(r[2]), "=r"(r[3]) : "r"(a));
}
__device__ __forceinline__ void mma_bf16(float* c, const uint32_t* a, const uint32_t* b) {
    asm volatile("mma.sync.aligned.m16n8k16.row.col.f32.bf16.bf16.f32 "
        "{%0,%1,%2,%3}, {%4,%5,%6,%7}, {%8,%9}, {%0,%1,%2,%3};"
        : "+f"(c[0]), "+f"(c[1]), "+f"(c[2]), "+f"(c[3])
        : "r"(a[0]), "r"(a[1]), "r"(a[2]), "r"(a[3]), "r"(b[0]), "r"(b[1]));
}
__device__ __forceinline__ void cp16(uint32_t saddr, const void* g) {
    asm volatile("cp.async.cg.shared.global [%0], [%1], 16;" :: "r"(saddr), "l"(g));
}
#define CP_COMMIT() asm volatile("cp.async.commit_group;" ::: "memory")
#define CP_WAIT(n)  asm volatile("cp.async.wait_group %0;" :: "n"(n) : "memory")

// hi/lo split
__device__ __forceinline__ void split2(float f, __nv_bfloat16& h, __nv_bfloat16& l) {
    h = __float2bfloat16(f);
    l = __float2bfloat16(f - __bfloat162float(h));
}

// ---------------------------------------------------------------------------
// SMEM layout: per stage, 4 tiles (Ah, Al, Bh, Bl), each 128 rows x 64 bf16
// padded to stride 72 bf16 (144 B). Tile = 18432 B, stage = 73728 B, x3 ring.
// 3 stages = 221184 B <= 227 KB max dynamic smem.
// ---------------------------------------------------------------------------
#define TSTRIDE_B 144
#define TILE_B    18432
#define BUF_B     73728
#define NSTAGE    3
#define SMEM_SZ   (NSTAGE*BUF_B)

// MODE 0: QKV  (A=x split, B=Wt split, N over 3072)
// MODE 1: scores (A=Q split, B=K split, causal tiles only)
// MODE 2: PV   (A=P split, B=Vt split, K truncated)
template<int MODE>
__global__ __launch_bounds__(256) void gemm_kernel(float* __restrict__ out)
{
    extern __shared__ char smem[];
    const uint32_t sb = smem_u32(smem);
    const int t = threadIdx.x;
    const int wid = t >> 5, lane = t & 31;
    const int m_warp = (wid & 1) * 64;
    const int n_warp = (wid >> 1) * 32;

    const __nv_bfloat16 *Ah, *Al, *Bh, *Bl;
    size_t sA, sB;
    int m0, n0, nchunks, b = 0;

    if (MODE == 0) {
        m0 = blockIdx.y * 128; n0 = blockIdx.x * 128;
        Ah = g_xh + (size_t)m0 * DIN;  Al = g_xl + (size_t)m0 * DIN;
        Bh = g_Wth + (size_t)n0 * DIN; Bl = g_Wtl + (size_t)n0 * DIN;
        sA = DIN; sB = DIN; nchunks = DIN / 64;
    } else if (MODE == 1) {
        b = blockIdx.y;
        int x = blockIdx.x, it = 0;
        while ((it + 1) * (it + 2) / 2 <= x) it++;
        int jt = x - it * (it + 1) / 2;
        m0 = it * 128; n0 = jt * 128;
        Ah = g_Qh + ((size_t)b * SEQ + m0) * DOUT; Al = g_Ql + ((size_t)b * SEQ + m0) * DOUT;
        Bh = g_Kh + ((size_t)b * SEQ + n0) * DOUT; Bl = g_Kl + ((size_t)b * SEQ + n0) * DOUT;
        sA = DOUT; sB = DOUT; nchunks = DOUT / 64;
    } else {
        b = blockIdx.z;
        m0 = blockIdx.y * 128; n0 = blockIdx.x * 128;
        Ah = g_Ph + ((size_t)b * SEQ + m0) * SEQ;  Al = g_Pl + ((size_t)b * SEQ + m0) * SEQ;
        Bh = g_Vth + ((size_t)b * DOUT + n0) * SEQ; Bl = g_Vtl + ((size_t)b * DOUT + n0) * SEQ;
        sA = SEQ; sB = SEQ; nchunks = (blockIdx.y + 1) * 2;   // >= 2 always
    }

    float acc[4][4][4] = {};   // [mt][nt][frag]

    // async chunk loader: 4 tiles x (128 rows x 8 x 16B) = 16 cp.async/thread
    auto issue_chunk = [&](int buf, int kc) {
        const int k0 = kc * 64;
        #pragma unroll
        for (int l = 0; l < 16; l++) {
            int tile = l >> 2;               // 0:Ah 1:Al 2:Bh 3:Bl
            int e    = (l & 3) * 256 + t;    // 0..1023
            int r    = e >> 3;
            int c8   = e & 7;
            const __nv_bfloat16* src = (tile == 0) ? Ah : (tile == 1) ? Al : (tile == 2) ? Bh : Bl;
            size_t stride = (tile < 2) ? sA : sB;
            cp16(sb + buf * BUF_B + tile * TILE_B + (uint32_t)(r * TSTRIDE_B + c8 * 16),
                 src + (size_t)r * stride + k0 + c8 * 8);
        }
        CP_COMMIT();
    };

    // prefetch distance 2 (nchunks >= 2 in every mode)
    issue_chunk(0, 0);
    issue_chunk(1, 1);

    int cbuf = 0;
    for (int c = 0; c < nchunks; c++) {
        if (c + 1 < nchunks) { CP_WAIT(1); } else { CP_WAIT(0); }
        // Single barrier per chunk: confirms chunk c resident AND all warps
        // finished reading stage (c-1)%3 (computed last iteration).
        __syncthreads();
        // Stage for c+2 is (c+2)%3 == (c-1)%3 — just freed. Issue now so the
        // loads overlap THIS chunk's MMA work.
        if (c + 2 < nchunks) {
            int nb = cbuf + 2; if (nb >= NSTAGE) nb -= NSTAGE;
            issue_chunk(nb, c + 2);
        }

        const uint32_t base = sb + cbuf * BUF_B;
        const int arow = m_warp + (lane & 7) + ((lane >> 3) & 1) * 8;
        const uint32_t acol = (lane >> 4) * 16;
        // B via ldsm4 over an nt-pair: matrix i of x4 = {n0-7/k0-7, n0-7/k8-15,
        // n8-15/k0-7, n8-15/k8-15} -> frags for nt=2p and nt=2p+1.
        const int brow4 = n_warp + (lane & 7) + (lane >> 4) * 8;
        const uint32_t bcol4 = ((lane >> 3) & 1) * 16;

        #pragma unroll
        for (int ks = 0; ks < 4; ks++) {
            const uint32_t kb = ks * 32;     // 16 bf16 = 32 bytes
            uint32_t bh[4][2], bl[4][2];
            #pragma unroll
            for (int p = 0; p < 2; p++) {
                uint32_t addr = base + 2 * TILE_B + (uint32_t)(brow4 + p * 16) * TSTRIDE_B + bcol4 + kb;
                uint32_t r4[4];
                ldsm4(r4, addr);
                bh[2*p][0] = r4[0]; bh[2*p][1] = r4[1];
                bh[2*p+1][0] = r4[2]; bh[2*p+1][1] = r4[3];
                ldsm4(r4, addr + TILE_B);
                bl[2*p][0] = r4[0]; bl[2*p][1] = r4[1];
                bl[2*p+1][0] = r4[2]; bl[2*p+1][1] = r4[3];
            }
            #pragma unroll
            for (int mt = 0; mt < 4; mt++) {
                uint32_t addr = base + (uint32_t)(arow + mt * 16) * TSTRIDE_B + acol + kb;
                uint32_t ah[4], al[4];
                ldsm4(ah, addr);
                ldsm4(al, addr + TILE_B);
                #pragma unroll
                for (int nt = 0; nt < 4; nt++) {
                    mma_bf16(acc[mt][nt], ah, bh[nt]);
                    mma_bf16(acc[mt][nt], ah, bl[nt]);
                    mma_bf16(acc[mt][nt], al, bh[nt]);
                }
            }
        }
        if (++cbuf >= NSTAGE) cbuf = 0;
    }

    // ---------------- epilogue straight from registers ----------------
    const int r_loc = m_warp + (lane >> 2);          // local row (of 128), +8 pair
    const int c_loc = n_warp + (lane & 3) * 2;       // local col (of 128)

    #pragma unroll
    for (int mt = 0; mt < 4; mt++) {
        #pragma unroll
        for (int half = 0; half < 2; half++) {
            int r = m0 + r_loc + mt * 16 + half * 8;
            #pragma unroll
            for (int nt = 0; nt < 4; nt++) {
                int cc = n0 + c_loc + nt * 8;
                float v0 = acc[mt][nt][half * 2 + 0];
                float v1 = acc[mt][nt][half * 2 + 1];

                if (MODE == 0) {
                    int mat = n0 >> 10;              // tile-uniform: 0=Q 1=K 2=V
                    int nl = cc & 1023;
                    float f0 = v0 + g_bcat[cc];
                    float f1 = v1 + g_bcat[cc + 1];
                    if (mat == 2) {
                        *(float2*)&g_V[(size_t)r * DOUT + nl] = make_float2(f0, f1);
                    } else {
                        __nv_bfloat16 h0, l0, h1, l1;
                        split2(f0, h0, l0); split2(f1, h1, l1);
                        __nv_bfloat162 hp; hp.x = h0; hp.y = h1;
                        __nv_bfloat162 lp; lp.x = l0; lp.y = l1;
                        __nv_bfloat16* H = (mat == 0) ? g_Qh : g_Kh;
                        __nv_bfloat16* L = (mat == 0) ? g_Ql : g_Kl;
                        *(__nv_bfloat162*)&H[(size_t)r * DOUT + nl] = hp;
                        *(__nv_bfloat162*)&L[(size_t)r * DOUT + nl] = lp;
                    }
                } else if (MODE == 1) {
                    const float scale = 0.03125f;    // 1/sqrt(1024)
                    float f0 = v0 * scale, f1 = v1 * scale;
                    if (m0 == n0) {                  // diagonal tile: mask j>i
                        if (cc     > r) f0 = -INFINITY;
                        if (cc + 1 > r) f1 = -INFINITY;
                    }
                    *(float2*)&g_S[((size_t)b * SEQ + r) * SEQ + cc] = make_float2(f0, f1);
                } else {
                    *(float2*)&out[((size_t)b * SEQ + r) * DOUT + cc] = make_float2(v0, v1);
                }
            }
        }
    }
}

// ---------------------------------------------------------------------------
// Prep kernels
// ---------------------------------------------------------------------------
__global__ __launch_bounds__(256) void prep_x_kernel(const float* __restrict__ x)
{
    size_t i = (size_t)blockIdx.x * 1024 + threadIdx.x * 4;
    float4 v = *(const float4*)&x[i];
    __nv_bfloat16 h, l;
    split2(v.x, h, l); g_xh[i + 0] = h; g_xl[i + 0] = l;
    split2(v.y, h, l); g_xh[i + 1] = h; g_xl[i + 1] = l;
    split2(v.z, h, l); g_xh[i + 2] = h; g_xl[i + 2] = l;
    split2(v.w, h, l); g_xh[i + 3] = h; g_xl[i + 3] = l;
}

__global__ void prep_bias_kernel(const float* __restrict__ bq,
                                 const float* __restrict__ bk,
                                 const float* __restrict__ bv)
{
    int i = blockIdx.x * 256 + threadIdx.x;   // 0..3071
    g_bcat[i] = (i < 1024) ? bq[i] : (i < 2048) ? bk[i - 1024] : bv[i - 2048];
}

// W [k][n] -> Wt [z*1024 + n][k], split
__global__ void prep_wt_kernel(const float* __restrict__ Wq,
                               const float* __restrict__ Wk,
                               const float* __restrict__ Wv)
{
    __shared__ float tl[32][33];
    const int z = blockIdx.z;
    const float* W = (z == 0) ? Wq : (z == 1) ? Wk : Wv;
    int kk = blockIdx.y * 32, nn = blockIdx.x * 32;
    int tx = threadIdx.x, ty = threadIdx.y;
    #pragma unroll
    for (int i = 0; i < 4; i++)
        tl[ty + i * 8][tx] = W[(size_t)(kk + ty + i * 8) * DOUT + nn + tx];
    __syncthreads();
    #pragma unroll
    for (int i = 0; i < 4; i++) {
        float f = tl[tx][ty + i * 8];        // = W[kk+tx][nn+ty+i*8]
        size_t row = (size_t)z * 1024 + nn + ty + i * 8;
        __nv_bfloat16 h, l; split2(f, h, l);
        g_Wth[row * DIN + kk + tx] = h;
        g_Wtl[row * DIN + kk + tx] = l;
    }
}

// V [b][j][d] -> Vt [b][d][j], split
__global__ void vtrans_kernel()
{
    __shared__ float tl[32][33];
    const int bz = blockIdx.z;
    int jj = blockIdx.x * 32, dd = blockIdx.y * 32;
    int tx = threadIdx.x, ty = threadIdx.y;
    #pragma unroll
    for (int i = 0; i < 4; i++)
        tl[ty + i * 8][tx] = g_V[((size_t)bz * SEQ + jj + ty + i * 8) * DOUT + dd + tx];
    __syncthreads();
    #pragma unroll
    for (int i = 0; i < 4; i++) {
        float f = tl[tx][ty + i * 8];        // = V[jj+tx][dd+ty+i*8]
        size_t row = (size_t)bz * DOUT + dd + ty + i * 8;
        __nv_bfloat16 h, l; split2(f, h, l);
        g_Vth[row * SEQ + jj + tx] = h;
        g_Vtl[row * SEQ + jj + tx] = l;
    }
}

// ---------------------------------------------------------------------------
// Softmax + P split; writes only the causally live region (j < row_end)
// ---------------------------------------------------------------------------
__device__ __forceinline__ float wr_max(float v) {
    #pragma unroll
    for (int o = 16; o > 0; o >>= 1) v = fmaxf(v, __shfl_xor_sync(0xFFFFFFFFu, v, o));
    return v;
}
__device__ __forceinline__ float wr_sum(float v) {
    #pragma unroll
    for (int o = 16; o > 0; o >>= 1) v += __shfl_xor_sync(0xFFFFFFFFu, v, o);
    return v;
}

__global__ __launch_bounds__(256) void softmax_split_kernel()
{
    const size_t row = blockIdx.x;          // b*SEQ + i
    const int i_in_b = (int)(row & (SEQ - 1));
    const int row_end = ((i_in_b >> 7) + 1) << 7;   // written (tile) region
    const float* Srow = g_S + row * SEQ;
    const int t = threadIdx.x;
    __shared__ float red[8];

    float vals[8];
    float mx = -INFINITY;
    #pragma unroll
    for (int l = 0; l < 8; l++) {
        int j = t + l * 256;
        vals[l] = (j < row_end) ? Srow[j] : -INFINITY;
        mx = fmaxf(mx, vals[l]);
    }
    mx = wr_max(mx);
    if ((t & 31) == 0) red[t >> 5] = mx;
    __syncthreads();
    if (t < 8) {
        float v = red[t];
        #pragma unroll
        for (int o = 4; o > 0; o >>= 1) v = fmaxf(v, __shfl_xor_sync(0xFFu, v, o));
        red[t] = v;
    }
    __syncthreads();
    mx = red[0];

    float sum = 0.f;
    #pragma unroll
    for (int l = 0; l < 8; l++) {
        float e = (vals[l] == -INFINITY) ? 0.f : __expf(vals[l] - mx);
        vals[l] = e;
        sum += e;
    }
    sum = wr_sum(sum);
    __syncthreads();
    if ((t & 31) == 0) red[t >> 5] = sum;
    __syncthreads();
    if (t < 8) {
        float v = red[t];
        #pragma unroll
        for (int o = 4; o > 0; o >>= 1) v += __shfl_xor_sync(0xFFu, v, o);
        red[t] = v;
    }
    __syncthreads();
    const float inv = 1.f / red[0];

    #pragma unroll
    for (int l = 0; l < 8; l++) {
        int j = t + l * 256;
        if (j < row_end) {
            float p = vals[l] * inv;
            __nv_bfloat16 h, lo; split2(p, h, lo);
            g_Ph[row * SEQ + j] = h;
            g_Pl[row * SEQ + j] = lo;
        }
    }
}

// ---------------------------------------------------------------------------
extern "C" void kernel_launch(void* const* d_in, const int* in_sizes, int n_in,
                              void* d_out, int out_size)
{
    const float* x  = (const float*)d_in[0];
    const float* Wq = (const float*)d_in[1];
    const float* bq = (const float*)d_in[2];
    const float* Wk = (const float*)d_in[3];
    const float* bk = (const float*)d_in[4];
    const float* Wv = (const float*)d_in[5];
    const float* bv = (const float*)d_in[6];
    float* out = (float*)d_out;

    cudaFuncSetAttribute(gemm_kernel<0>, cudaFuncAttributeMaxDynamicSharedMemorySize, SMEM_SZ);
    cudaFuncSetAttribute(gemm_kernel<1>, cudaFuncAttributeMaxDynamicSharedMemorySize, SMEM_SZ);
    cudaFuncSetAttribute(gemm_kernel<2>, cudaFuncAttributeMaxDynamicSharedMemorySize, SMEM_SZ);

    prep_x_kernel<<<MTOT * DIN / 1024, 256>>>(x);
    prep_bias_kernel<<<NCAT / 256, 256>>>(bq, bk, bv);
    prep_wt_kernel<<<dim3(DOUT / 32, DIN / 32, 3), dim3(32, 8)>>>(Wq, Wk, Wv);

    // QKV: N = 3072 concat, M = 8192
    gemm_kernel<0><<<dim3(NCAT / 128, MTOT / 128), 256, SMEM_SZ>>>(out);

    vtrans_kernel<<<dim3(SEQ / 32, DOUT / 32, BATCH), dim3(32, 8)>>>();

    // Scores: lower-triangular tiles only (16*17/2 = 136 per batch)
    gemm_kernel<1><<<dim3(136, BATCH), 256, SMEM_SZ>>>(out);

    softmax_split_kernel<<<BATCH * SEQ, 256>>>();

    // PV: K truncated by causality inside kernel
    gemm_kernel<2><<<dim3(DOUT / 128, SEQ / 128, BATCH), 256, SMEM_SZ>>>(out);
}

// round 12
// speedup vs baseline: 4.3630x; 1.0120x over previous
#include <cuda_runtime.h>
#include <cuda_bf16.h>
#include <math.h>
#include <stdint.h>

#define BATCH 4
#define SEQ   2048
#define DIN   1024
#define DOUT  1024
#define MTOT  (BATCH*SEQ)            // 8192
#define NCAT  (3*DOUT)               // 3072

// ---------------------------------------------------------------------------
// Scratch (device globals)
// ---------------------------------------------------------------------------
__device__ __nv_bfloat16 g_xh[(size_t)MTOT*DIN];
__device__ __nv_bfloat16 g_xl[(size_t)MTOT*DIN];
__device__ __nv_bfloat16 g_Wth[(size_t)NCAT*DIN];   // W^T concat [n][k]
__device__ __nv_bfloat16 g_Wtl[(size_t)NCAT*DIN];
__device__ float         g_bcat[NCAT];
__device__ __nv_bfloat16 g_Qh[(size_t)MTOT*DOUT];
__device__ __nv_bfloat16 g_Ql[(size_t)MTOT*DOUT];
__device__ __nv_bfloat16 g_Kh[(size_t)MTOT*DOUT];
__device__ __nv_bfloat16 g_Kl[(size_t)MTOT*DOUT];
__device__ float         g_V [(size_t)MTOT*DOUT];
__device__ __nv_bfloat16 g_Vth[(size_t)BATCH*DOUT*SEQ];  // V^T [b][d][j]
__device__ __nv_bfloat16 g_Vtl[(size_t)BATCH*DOUT*SEQ];
__device__ float         g_S [(size_t)BATCH*SEQ*SEQ];
__device__ __nv_bfloat16 g_Ph[(size_t)BATCH*SEQ*SEQ];
__device__ __nv_bfloat16 g_Pl[(size_t)BATCH*SEQ*SEQ];

// ---------------------------------------------------------------------------
// Baseline-PTX tensor helpers (mma.sync + ldmatrix + cp.async; plain sm_103)
// ---------------------------------------------------------------------------
__device__ __forceinline__ uint32_t smem_u32(const void* p) {
    uint32_t a;
    asm("{ .reg .u64 t; cvta.to.shared.u64 t, %1; cvt.u32.u64 %0, t; }" : "=r"(a) : "l"(p));
    return a;
}
__device__ __forceinline__ void ldsm4(uint32_t* r, uint32_t a) {
    asm volatile("ldmatrix.sync.aligned.m8n8.x4.shared.b16 {%0,%1,%2,%3}, [%4];"
        : "=r"(r[0]), "=r"(r[1]), "=r"(r[2]), "=r"(r[3]) : "r"(a));
}
__device__ __forceinline__ void mma_bf16(float* c, const uint32_t* a, const uint32_t* b) {
    asm volatile("mma.sync.aligned.m16n8k16.row.col.f32.bf16.bf16.f32 "
        "{%0,%1,%2,%3}, {%4,%5,%6,%7}, {%8,%9}, {%0,%1,%2,%3};"
        : "+f"(c[0]), "+f"(c[1]), "+f"(c[2]), "+f"(c[3])
        : "r"(a[0]), "r"(a[1]), "r"(a[2]), "r"(a[3]), "r"(b[0]), "r"(b[1]));
}
__device__ __forceinline__ void cp16(uint32_t saddr, const void* g) {
    asm volatile("cp.async.cg.shared.global [%0], [%1], 16;" :: "r"(saddr), "l"(g));
}
#define CP_COMMIT() asm volatile("cp.async.commit_group;" ::: "memory")
#define CP_WAIT(n)  asm volatile("cp.async.wait_group %0;" :: "n"(n) : "memory")

// hi/lo split
__device__ __forceinline__ void split2(float f, __nv_bfloat16& h, __nv_bfloat16& l) {
    h = __float2bfloat16(f);
    l = __float2bfloat16(f - __bfloat162float(h));
}

// ---------------------------------------------------------------------------
// SMEM layout: per stage, 4 tiles (Ah, Al, Bh, Bl), each 128 rows x 64 bf16
// padded to stride 72 bf16 (144 B). Tile = 18432 B, stage = 73728 B, x3 ring.
// ---------------------------------------------------------------------------
#define TSTRIDE_B 144
#define TILE_B    18432
#define BUF_B     73728
#define NSTAGE    3
#define SMEM_SZ   (NSTAGE*BUF_B)
#define NTHREADS  512

// MODE 0: QKV  (A=x split, B=Wt split, N over 3072)
// MODE 1: scores (A=Q split, B=K split, causal tiles only)
// MODE 2: PV   (A=P split, B=Vt split, K truncated)
template<int MODE>
__global__ __launch_bounds__(NTHREADS) void gemm_kernel(float* __restrict__ out)
{
    extern __shared__ char smem[];
    const uint32_t sb = smem_u32(smem);
    const int t = threadIdx.x;
    const int wid = t >> 5, lane = t & 31;
    // 16 warps in a 4x4 grid; each warp owns a 32x32 subtile.
    const int m_warp = (wid & 3) * 32;
    const int n_warp = (wid >> 2) * 32;

    const __nv_bfloat16 *Ah, *Al, *Bh, *Bl;
    size_t sA, sB;
    int m0, n0, nchunks, b = 0;

    if (MODE == 0) {
        m0 = blockIdx.y * 128; n0 = blockIdx.x * 128;
        Ah = g_xh + (size_t)m0 * DIN;  Al = g_xl + (size_t)m0 * DIN;
        Bh = g_Wth + (size_t)n0 * DIN; Bl = g_Wtl + (size_t)n0 * DIN;
        sA = DIN; sB = DIN; nchunks = DIN / 64;
    } else if (MODE == 1) {
        b = blockIdx.y;
        int x = blockIdx.x, it = 0;
        while ((it + 1) * (it + 2) / 2 <= x) it++;
        int jt = x - it * (it + 1) / 2;
        m0 = it * 128; n0 = jt * 128;
        Ah = g_Qh + ((size_t)b * SEQ + m0) * DOUT; Al = g_Ql + ((size_t)b * SEQ + m0) * DOUT;
        Bh = g_Kh + ((size_t)b * SEQ + n0) * DOUT; Bl = g_Kl + ((size_t)b * SEQ + n0) * DOUT;
        sA = DOUT; sB = DOUT; nchunks = DOUT / 64;
    } else {
        b = blockIdx.z;
        m0 = blockIdx.y * 128; n0 = blockIdx.x * 128;
        Ah = g_Ph + ((size_t)b * SEQ + m0) * SEQ;  Al = g_Pl + ((size_t)b * SEQ + m0) * SEQ;
        Bh = g_Vth + ((size_t)b * DOUT + n0) * SEQ; Bl = g_Vtl + ((size_t)b * DOUT + n0) * SEQ;
        sA = SEQ; sB = SEQ; nchunks = (blockIdx.y + 1) * 2;   // >= 2 always
    }

    float acc[2][4][4] = {};   // [mt][nt][frag], 32 regs

    // async chunk loader: 4 tiles x 1024 x 16B = 8 cp.async per thread (512 thr)
    auto issue_chunk = [&](int buf, int kc) {
        const int k0 = kc * 64;
        #pragma unroll
        for (int l = 0; l < 8; l++) {
            int tile = l >> 1;               // 0:Ah 1:Al 2:Bh 3:Bl
            int e    = (l & 1) * 512 + t;    // 0..1023
            int r    = e >> 3;
            int c8   = e & 7;
            const __nv_bfloat16* src = (tile == 0) ? Ah : (tile == 1) ? Al : (tile == 2) ? Bh : Bl;
            size_t stride = (tile < 2) ? sA : sB;
            cp16(sb + buf * BUF_B + tile * TILE_B + (uint32_t)(r * TSTRIDE_B + c8 * 16),
                 src + (size_t)r * stride + k0 + c8 * 8);
        }
        CP_COMMIT();
    };

    // prefetch distance 2 (nchunks >= 2 in every mode)
    issue_chunk(0, 0);
    issue_chunk(1, 1);

    int cbuf = 0;
    for (int c = 0; c < nchunks; c++) {
        if (c + 1 < nchunks) { CP_WAIT(1); } else { CP_WAIT(0); }
        __syncthreads();                     // chunk c resident; stage (c-1)%3 free
        if (c + 2 < nchunks) {
            int nb = cbuf + 2; if (nb >= NSTAGE) nb -= NSTAGE;
            issue_chunk(nb, c + 2);          // overlaps this chunk's MMAs
        }

        const uint32_t base = sb + cbuf * BUF_B;
        const int arow = m_warp + (lane & 7) + ((lane >> 3) & 1) * 8;
        const uint32_t acol = (lane >> 4) * 16;
        // B ldsm4 over an nt-pair (16 n-rows x 16 k)
        const int brow4 = n_warp + (lane & 7) + (lane >> 4) * 8;
        const uint32_t bcol4 = ((lane >> 3) & 1) * 16;

        #pragma unroll
        for (int ks = 0; ks < 4; ks++) {
            const uint32_t kb = ks * 32;     // 16 bf16 = 32 bytes
            uint32_t bh[4][2], bl[4][2];
            #pragma unroll
            for (int p = 0; p < 2; p++) {
                uint32_t addr = base + 2 * TILE_B + (uint32_t)(brow4 + p * 16) * TSTRIDE_B + bcol4 + kb;
                uint32_t r4[4];
                ldsm4(r4, addr);
                bh[2*p][0] = r4[0]; bh[2*p][1] = r4[1];
                bh[2*p+1][0] = r4[2]; bh[2*p+1][1] = r4[3];
                ldsm4(r4, addr + TILE_B);
                bl[2*p][0] = r4[0]; bl[2*p][1] = r4[1];
                bl[2*p+1][0] = r4[2]; bl[2*p+1][1] = r4[3];
            }
            #pragma unroll
            for (int mt = 0; mt < 2; mt++) {
                uint32_t addr = base + (uint32_t)(arow + mt * 16) * TSTRIDE_B + acol + kb;
                uint32_t ah[4], al[4];
                ldsm4(ah, addr);
                ldsm4(al, addr + TILE_B);
                // product-major order: each acc's 3 dependent MMAs are
                // separated by 3 independent ones (breaks RAW chains)
                #pragma unroll
                for (int nt = 0; nt < 4; nt++) mma_bf16(acc[mt][nt], ah, bh[nt]);
                #pragma unroll
                for (int nt = 0; nt < 4; nt++) mma_bf16(acc[mt][nt], ah, bl[nt]);
                #pragma unroll
                for (int nt = 0; nt < 4; nt++) mma_bf16(acc[mt][nt], al, bh[nt]);
            }
        }
        if (++cbuf >= NSTAGE) cbuf = 0;
    }

    // ---------------- epilogue straight from registers ----------------
    const int r_loc = m_warp + (lane >> 2);          // local row (of 128), +8 pair
    const int c_loc = n_warp + (lane & 3) * 2;       // local col (of 128)

    #pragma unroll
    for (int mt = 0; mt < 2; mt++) {
        #pragma unroll
        for (int half = 0; half < 2; half++) {
            int r = m0 + r_loc + mt * 16 + half * 8;
            #pragma unroll
            for (int nt = 0; nt < 4; nt++) {
                int cc = n0 + c_loc + nt * 8;
                float v0 = acc[mt][nt][half * 2 + 0];
                float v1 = acc[mt][nt][half * 2 + 1];

                if (MODE == 0) {
                    int mat = n0 >> 10;              // tile-uniform: 0=Q 1=K 2=V
                    int nl = cc & 1023;
                    float f0 = v0 + g_bcat[cc];
                    float f1 = v1 + g_bcat[cc + 1];
                    if (mat == 2) {
                        *(float2*)&g_V[(size_t)r * DOUT + nl] = make_float2(f0, f1);
                    } else {
                        __nv_bfloat16 h0, l0, h1, l1;
                        split2(f0, h0, l0); split2(f1, h1, l1);
                        __nv_bfloat162 hp; hp.x = h0; hp.y = h1;
                        __nv_bfloat162 lp; lp.x = l0; lp.y = l1;
                        __nv_bfloat16* H = (mat == 0) ? g_Qh : g_Kh;
                        __nv_bfloat16* L = (mat == 0) ? g_Ql : g_Kl;
                        *(__nv_bfloat162*)&H[(size_t)r * DOUT + nl] = hp;
                        *(__nv_bfloat162*)&L[(size_t)r * DOUT + nl] = lp;
                    }
                } else if (MODE == 1) {
                    const float scale = 0.03125f;    // 1/sqrt(1024)
                    float f0 = v0 * scale, f1 = v1 * scale;
                    if (m0 == n0) {                  // diagonal tile: mask j>i
                        if (cc     > r) f0 = -INFINITY;
                        if (cc + 1 > r) f1 = -INFINITY;
                    }
                    *(float2*)&g_S[((size_t)b * SEQ + r) * SEQ + cc] = make_float2(f0, f1);
                } else {
                    *(float2*)&out[((size_t)b * SEQ + r) * DOUT + cc] = make_float2(v0, v1);
                }
            }
        }
    }
}

// ---------------------------------------------------------------------------
// Prep kernels
// ---------------------------------------------------------------------------
__global__ __launch_bounds__(256) void prep_x_kernel(const float* __restrict__ x)
{
    size_t i = (size_t)blockIdx.x * 1024 + threadIdx.x * 4;
    float4 v = *(const float4*)&x[i];
    __nv_bfloat16 h, l;
    split2(v.x, h, l); g_xh[i + 0] = h; g_xl[i + 0] = l;
    split2(v.y, h, l); g_xh[i + 1] = h; g_xl[i + 1] = l;
    split2(v.z, h, l); g_xh[i + 2] = h; g_xl[i + 2] = l;
    split2(v.w, h, l); g_xh[i + 3] = h; g_xl[i + 3] = l;
}

__global__ void prep_bias_kernel(const float* __restrict__ bq,
                                 const float* __restrict__ bk,
                                 const float* __restrict__ bv)
{
    int i = blockIdx.x * 256 + threadIdx.x;   // 0..3071
    g_bcat[i] = (i < 1024) ? bq[i] : (i < 2048) ? bk[i - 1024] : bv[i - 2048];
}

// W [k][n] -> Wt [z*1024 + n][k], split
__global__ void prep_wt_kernel(const float* __restrict__ Wq,
                               const float* __restrict__ Wk,
                               const float* __restrict__ Wv)
{
    __shared__ float tl[32][33];
    const int z = blockIdx.z;
    const float* W = (z == 0) ? Wq : (z == 1) ? Wk : Wv;
    int kk = blockIdx.y * 32, nn = blockIdx.x * 32;
    int tx = threadIdx.x, ty = threadIdx.y;
    #pragma unroll
    for (int i = 0; i < 4; i++)
        tl[ty + i * 8][tx] = W[(size_t)(kk + ty + i * 8) * DOUT + nn + tx];
    __syncthreads();
    #pragma unroll
    for (int i = 0; i < 4; i++) {
        float f = tl[tx][ty + i * 8];        // = W[kk+tx][nn+ty+i*8]
        size_t row = (size_t)z * 1024 + nn + ty + i * 8;
        __nv_bfloat16 h, l; split2(f, h, l);
        g_Wth[row * DIN + kk + tx] = h;
        g_Wtl[row * DIN + kk + tx] = l;
    }
}

// V [b][j][d] -> Vt [b][d][j], split
__global__ void vtrans_kernel()
{
    __shared__ float tl[32][33];
    const int bz = blockIdx.z;
    int jj = blockIdx.x * 32, dd = blockIdx.y * 32;
    int tx = threadIdx.x, ty = threadIdx.y;
    #pragma unroll
    for (int i = 0; i < 4; i++)
        tl[ty + i * 8][tx] = g_V[((size_t)bz * SEQ + jj + ty + i * 8) * DOUT + dd + tx];
    __syncthreads();
    #pragma unroll
    for (int i = 0; i < 4; i++) {
        float f = tl[tx][ty + i * 8];        // = V[jj+tx][dd+ty+i*8]
        size_t row = (size_t)bz * DOUT + dd + ty + i * 8;
        __nv_bfloat16 h, l; split2(f, h, l);
        g_Vth[row * SEQ + jj + tx] = h;
        g_Vtl[row * SEQ + jj + tx] = l;
    }
}

// ---------------------------------------------------------------------------
// Softmax + P split; writes only the causally live region (j < row_end)
// ---------------------------------------------------------------------------
__device__ __forceinline__ float wr_max(float v) {
    #pragma unroll
    for (int o = 16; o > 0; o >>= 1) v = fmaxf(v, __shfl_xor_sync(0xFFFFFFFFu, v, o));
    return v;
}
__device__ __forceinline__ float wr_sum(float v) {
    #pragma unroll
    for (int o = 16; o > 0; o >>= 1) v += __shfl_xor_sync(0xFFFFFFFFu, v, o);
    return v;
}

__global__ __launch_bounds__(256) void softmax_split_kernel()
{
    const size_t row = blockIdx.x;          // b*SEQ + i
    const int i_in_b = (int)(row & (SEQ - 1));
    const int row_end = ((i_in_b >> 7) + 1) << 7;   // written (tile) region
    const float* Srow = g_S + row * SEQ;
    const int t = threadIdx.x;
    __shared__ float red[8];

    float vals[8];
    float mx = -INFINITY;
    #pragma unroll
    for (int l = 0; l < 8; l++) {
        int j = t + l * 256;
        vals[l] = (j < row_end) ? Srow[j] : -INFINITY;
        mx = fmaxf(mx, vals[l]);
    }
    mx = wr_max(mx);
    if ((t & 31) == 0) red[t >> 5] = mx;
    __syncthreads();
    if (t < 8) {
        float v = red[t];
        #pragma unroll
        for (int o = 4; o > 0; o >>= 1) v = fmaxf(v, __shfl_xor_sync(0xFFu, v, o));
        red[t] = v;
    }
    __syncthreads();
    mx = red[0];

    float sum = 0.f;
    #pragma unroll
    for (int l = 0; l < 8; l++) {
        float e = (vals[l] == -INFINITY) ? 0.f : __expf(vals[l] - mx);
        vals[l] = e;
        sum += e;
    }
    sum = wr_sum(sum);
    __syncthreads();
    if ((t & 31) == 0) red[t >> 5] = sum;
    __syncthreads();
    if (t < 8) {
        float v = red[t];
        #pragma unroll
        for (int o = 4; o > 0; o >>= 1) v += __shfl_xor_sync(0xFFu, v, o);
        red[t] = v;
    }
    __syncthreads();
    const float inv = 1.f / red[0];

    #pragma unroll
    for (int l = 0; l < 8; l++) {
        int j = t + l * 256;
        if (j < row_end) {
            float p = vals[l] * inv;
            __nv_bfloat16 h, lo; split2(p, h, lo);
            g_Ph[row * SEQ + j] = h;
            g_Pl[row * SEQ + j] = lo;
        }
    }
}

// ---------------------------------------------------------------------------
extern "C" void kernel_launch(void* const* d_in, const int* in_sizes, int n_in,
                              void* d_out, int out_size)
{
    const float* x  = (const float*)d_in[0];
    const float* Wq = (const float*)d_in[1];
    const float* bq = (const float*)d_in[2];
    const float* Wk = (const float*)d_in[3];
    const float* bk = (const float*)d_in[4];
    const float* Wv = (const float*)d_in[5];
    const float* bv = (const float*)d_in[6];
    float* out = (float*)d_out;

    cudaFuncSetAttribute(gemm_kernel<0>, cudaFuncAttributeMaxDynamicSharedMemorySize, SMEM_SZ);
    cudaFuncSetAttribute(gemm_kernel<1>, cudaFuncAttributeMaxDynamicSharedMemorySize, SMEM_SZ);
    cudaFuncSetAttribute(gemm_kernel<2>, cudaFuncAttributeMaxDynamicSharedMemorySize, SMEM_SZ);

    prep_x_kernel<<<MTOT * DIN / 1024, 256>>>(x);
    prep_bias_kernel<<<NCAT / 256, 256>>>(bq, bk, bv);
    prep_wt_kernel<<<dim3(DOUT / 32, DIN / 32, 3), dim3(32, 8)>>>(Wq, Wk, Wv);

    // QKV: N = 3072 concat, M = 8192
    gemm_kernel<0><<<dim3(NCAT / 128, MTOT / 128), NTHREADS, SMEM_SZ>>>(out);

    vtrans_kernel<<<dim3(SEQ / 32, DOUT / 32, BATCH), dim3(32, 8)>>>();

    // Scores: lower-triangular tiles only (16*17/2 = 136 per batch)
    gemm_kernel<1><<<dim3(136, BATCH), NTHREADS, SMEM_SZ>>>(out);

    softmax_split_kernel<<<BATCH * SEQ, 256>>>();

    // PV: K truncated by causality inside kernel
    gemm_kernel<2><<<dim3(DOUT / 128, SEQ / 128, BATCH), NTHREADS, SMEM_SZ>>>(out);
}

// round 13
// speedup vs baseline: 5.8410x; 1.3388x over previous
#include <cuda_runtime.h>
#include <cuda_fp16.h>
#include <math.h>
#include <stdint.h>

#define BATCH 4
#define SEQ   2048
#define DIN   1024
#define DOUT  1024
#define MTOT  (BATCH*SEQ)            // 8192
#define NCAT  (3*DOUT)               // 3072

// ---------------------------------------------------------------------------
// Scratch (device globals). A-side operands are hi/lo fp16 pairs; B-side single.
// ---------------------------------------------------------------------------
__device__ __half g_xh[(size_t)MTOT*DIN];
__device__ __half g_xl[(size_t)MTOT*DIN];
__device__ __half g_Wth[(size_t)NCAT*DIN];          // W^T concat [n][k], single
__device__ float  g_bcat[NCAT];
__device__ __half g_Qh[(size_t)MTOT*DOUT];
__device__ __half g_Ql[(size_t)MTOT*DOUT];
__device__ __half g_Kh[(size_t)MTOT*DOUT];          // single (B side of scores)
__device__ float  g_V [(size_t)MTOT*DOUT];
__device__ __half g_Vth[(size_t)BATCH*DOUT*SEQ];    // V^T [b][d][j], single
__device__ float  g_S [(size_t)BATCH*SEQ*SEQ];
__device__ __half g_Ph[(size_t)BATCH*SEQ*SEQ];
__device__ __half g_Pl[(size_t)BATCH*SEQ*SEQ];

// ---------------------------------------------------------------------------
// Baseline-PTX tensor helpers (mma.sync + ldmatrix + cp.async; plain sm_103)
// ---------------------------------------------------------------------------
__device__ __forceinline__ uint32_t smem_u32(const void* p) {
    uint32_t a;
    asm("{ .reg .u64 t; cvta.to.shared.u64 t, %1; cvt.u32.u64 %0, t; }" : "=r"(a) : "l"(p));
    return a;
}
__device__ __forceinline__ void ldsm4(uint32_t* r, uint32_t a) {
    asm volatile("ldmatrix.sync.aligned.m8n8.x4.shared.b16 {%0,%1,%2,%3}, [%4];"
        : "=r"(r[0]), "=r"(r[1]), "=r"(r[2]), "=r"(r[3]) : "r"(a));
}
__device__ __forceinline__ void mma_f16(float* c, const uint32_t* a, const uint32_t* b) {
    asm volatile("mma.sync.aligned.m16n8k16.row.col.f32.f16.f16.f32 "
        "{%0,%1,%2,%3}, {%4,%5,%6,%7}, {%8,%9}, {%0,%1,%2,%3};"
        : "+f"(c[0]), "+f"(c[1]), "+f"(c[2]), "+f"(c[3])
        : "r"(a[0]), "r"(a[1]), "r"(a[2]), "r"(a[3]), "r"(b[0]), "r"(b[1]));
}
__device__ __forceinline__ void cp16(uint32_t saddr, const void* g) {
    asm volatile("cp.async.cg.shared.global [%0], [%1], 16;" :: "r"(saddr), "l"(g));
}
#define CP_COMMIT() asm volatile("cp.async.commit_group;" ::: "memory")
#define CP_WAIT(n)  asm volatile("cp.async.wait_group %0;" :: "n"(n) : "memory")

// fp16 hi/lo split (A-side, ~22 effective mantissa bits)
__device__ __forceinline__ void split2h(float f, __half& h, __half& l) {
    h = __float2half(f);
    l = __float2half(f - __half2float(h));
}

// ---------------------------------------------------------------------------
// SMEM: per stage 3 tiles (Ah, Al, Bh), each 128 rows x 64 fp16, stride 144 B.
// Stage = 55296 B, 4-stage ring = 221184 B.
// ---------------------------------------------------------------------------
#define TSTRIDE_B 144
#define TILE_B    18432
#define STAGE_B   (3*TILE_B)
#define NSTAGE    4
#define SMEM_SZ   (NSTAGE*STAGE_B)
#define NTHREADS  512

// MODE 0: QKV  (A=x split, B=Wt single, N over 3072)
// MODE 1: scores (A=Q split, B=K single, causal tiles only)
// MODE 2: PV   (A=P split, B=Vt single, K truncated)
template<int MODE>
__global__ __launch_bounds__(NTHREADS) void gemm_kernel(float* __restrict__ out)
{
    extern __shared__ char smem[];
    const uint32_t sb = smem_u32(smem);
    const int t = threadIdx.x;
    const int wid = t >> 5, lane = t & 31;
    // 16 warps in a 4x4 grid; each warp owns a 32x32 subtile.
    const int m_warp = (wid & 3) * 32;
    const int n_warp = (wid >> 2) * 32;

    const __half *Ah, *Al, *Bh;
    size_t sA, sB;
    int m0, n0, nchunks, b = 0;

    if (MODE == 0) {
        m0 = blockIdx.y * 128; n0 = blockIdx.x * 128;
        Ah = g_xh + (size_t)m0 * DIN;  Al = g_xl + (size_t)m0 * DIN;
        Bh = g_Wth + (size_t)n0 * DIN;
        sA = DIN; sB = DIN; nchunks = DIN / 64;
    } else if (MODE == 1) {
        b = blockIdx.y;
        int x = blockIdx.x, it = 0;
        while ((it + 1) * (it + 2) / 2 <= x) it++;
        int jt = x - it * (it + 1) / 2;
        m0 = it * 128; n0 = jt * 128;
        Ah = g_Qh + ((size_t)b * SEQ + m0) * DOUT; Al = g_Ql + ((size_t)b * SEQ + m0) * DOUT;
        Bh = g_Kh + ((size_t)b * SEQ + n0) * DOUT;
        sA = DOUT; sB = DOUT; nchunks = DOUT / 64;
    } else {
        b = blockIdx.z;
        m0 = blockIdx.y * 128; n0 = blockIdx.x * 128;
        Ah = g_Ph + ((size_t)b * SEQ + m0) * SEQ;  Al = g_Pl + ((size_t)b * SEQ + m0) * SEQ;
        Bh = g_Vth + ((size_t)b * DOUT + n0) * SEQ;
        sA = SEQ; sB = SEQ; nchunks = (blockIdx.y + 1) * 2;   // >= 2 always
    }

    float acc[2][4][4] = {};   // [mt][nt][frag], 32 regs

    // async chunk loader: 3 tiles x 1024 x 16B = 6 cp.async per thread (512 thr)
    auto issue_chunk = [&](int buf, int kc) {
        const int k0 = kc * 64;
        #pragma unroll
        for (int l = 0; l < 6; l++) {
            int tile = l >> 1;               // 0:Ah 1:Al 2:Bh
            int e    = (l & 1) * 512 + t;    // 0..1023
            int r    = e >> 3;
            int c8   = e & 7;
            const __half* src = (tile == 0) ? Ah : (tile == 1) ? Al : Bh;
            size_t stride = (tile < 2) ? sA : sB;
            cp16(sb + buf * STAGE_B + tile * TILE_B + (uint32_t)(r * TSTRIDE_B + c8 * 16),
                 src + (size_t)r * stride + k0 + c8 * 8);
        }
        CP_COMMIT();
    };

    // prologue: prefetch up to NSTAGE-1 = 3 chunks
    const int npro = (nchunks < NSTAGE - 1) ? nchunks : (NSTAGE - 1);
    for (int kc = 0; kc < npro; kc++) issue_chunk(kc, kc);

    for (int c = 0; c < nchunks; c++) {
        const int rem = nchunks - 1 - c;
        if (rem >= 2)      { CP_WAIT(2); }
        else if (rem == 1) { CP_WAIT(1); }
        else               { CP_WAIT(0); }
        __syncthreads();                     // chunk c resident; stage (c-1)%4 free
        if (c + NSTAGE - 1 < nchunks)
            issue_chunk((c + NSTAGE - 1) % NSTAGE, c + NSTAGE - 1);

        const uint32_t base = sb + (c % NSTAGE) * STAGE_B;
        const int arow = m_warp + (lane & 7) + ((lane >> 3) & 1) * 8;
        const uint32_t acol = (lane >> 4) * 16;
        // B ldsm4 over an nt-pair (16 n-rows x 16 k)
        const int brow4 = n_warp + (lane & 7) + (lane >> 4) * 8;
        const uint32_t bcol4 = ((lane >> 3) & 1) * 16;

        #pragma unroll
        for (int ks = 0; ks < 4; ks++) {
            const uint32_t kb = ks * 32;     // 16 fp16 = 32 bytes
            uint32_t bh[4][2];
            #pragma unroll
            for (int p = 0; p < 2; p++) {
                uint32_t addr = base + 2 * TILE_B + (uint32_t)(brow4 + p * 16) * TSTRIDE_B + bcol4 + kb;
                uint32_t r4[4];
                ldsm4(r4, addr);
                bh[2*p][0] = r4[0]; bh[2*p][1] = r4[1];
                bh[2*p+1][0] = r4[2]; bh[2*p+1][1] = r4[3];
            }
            #pragma unroll
            for (int mt = 0; mt < 2; mt++) {
                uint32_t addr = base + (uint32_t)(arow + mt * 16) * TSTRIDE_B + acol + kb;
                uint32_t ah[4], al[4];
                ldsm4(ah, addr);
                ldsm4(al, addr + TILE_B);
                #pragma unroll
                for (int nt = 0; nt < 4; nt++) mma_f16(acc[mt][nt], ah, bh[nt]);
                #pragma unroll
                for (int nt = 0; nt < 4; nt++) mma_f16(acc[mt][nt], al, bh[nt]);
            }
        }
    }

    // ---------------- epilogue straight from registers ----------------
    const int r_loc = m_warp + (lane >> 2);          // local row (of 128), +8 pair
    const int c_loc = n_warp + (lane & 3) * 2;       // local col (of 128)

    #pragma unroll
    for (int mt = 0; mt < 2; mt++) {
        #pragma unroll
        for (int half = 0; half < 2; half++) {
            int r = m0 + r_loc + mt * 16 + half * 8;
            #pragma unroll
            for (int nt = 0; nt < 4; nt++) {
                int cc = n0 + c_loc + nt * 8;
                float v0 = acc[mt][nt][half * 2 + 0];
                float v1 = acc[mt][nt][half * 2 + 1];

                if (MODE == 0) {
                    int mat = n0 >> 10;              // tile-uniform: 0=Q 1=K 2=V
                    int nl = cc & 1023;
                    float f0 = v0 + g_bcat[cc];
                    float f1 = v1 + g_bcat[cc + 1];
                    if (mat == 2) {
                        *(float2*)&g_V[(size_t)r * DOUT + nl] = make_float2(f0, f1);
                    } else if (mat == 1) {           // K: single fp16 (B side)
                        __half2 kp; kp.x = __float2half(f0); kp.y = __float2half(f1);
                        *(__half2*)&g_Kh[(size_t)r * DOUT + nl] = kp;
                    } else {                         // Q: hi/lo split (A side)
                        __half h0, l0, h1, l1;
                        split2h(f0, h0, l0); split2h(f1, h1, l1);
                        __half2 hp; hp.x = h0; hp.y = h1;
                        __half2 lp; lp.x = l0; lp.y = l1;
                        *(__half2*)&g_Qh[(size_t)r * DOUT + nl] = hp;
                        *(__half2*)&g_Ql[(size_t)r * DOUT + nl] = lp;
                    }
                } else if (MODE == 1) {
                    const float scale = 0.03125f;    // 1/sqrt(1024)
                    float f0 = v0 * scale, f1 = v1 * scale;
                    if (m0 == n0) {                  // diagonal tile: mask j>i
                        if (cc     > r) f0 = -INFINITY;
                        if (cc + 1 > r) f1 = -INFINITY;
                    }
                    *(float2*)&g_S[((size_t)b * SEQ + r) * SEQ + cc] = make_float2(f0, f1);
                } else {
                    *(float2*)&out[((size_t)b * SEQ + r) * DOUT + cc] = make_float2(v0, v1);
                }
            }
        }
    }
}

// ---------------------------------------------------------------------------
// Prep kernels
// ---------------------------------------------------------------------------
__global__ __launch_bounds__(256) void prep_x_kernel(const float* __restrict__ x)
{
    size_t i = (size_t)blockIdx.x * 1024 + threadIdx.x * 4;
    float4 v = *(const float4*)&x[i];
    __half h, l;
    split2h(v.x, h, l); g_xh[i + 0] = h; g_xl[i + 0] = l;
    split2h(v.y, h, l); g_xh[i + 1] = h; g_xl[i + 1] = l;
    split2h(v.z, h, l); g_xh[i + 2] = h; g_xl[i + 2] = l;
    split2h(v.w, h, l); g_xh[i + 3] = h; g_xl[i + 3] = l;
}

__global__ void prep_bias_kernel(const float* __restrict__ bq,
                                 const float* __restrict__ bk,
                                 const float* __restrict__ bv)
{
    int i = blockIdx.x * 256 + threadIdx.x;   // 0..3071
    g_bcat[i] = (i < 1024) ? bq[i] : (i < 2048) ? bk[i - 1024] : bv[i - 2048];
}

// W [k][n] -> Wt [z*1024 + n][k], single fp16 (B side)
__global__ void prep_wt_kernel(const float* __restrict__ Wq,
                               const float* __restrict__ Wk,
                               const float* __restrict__ Wv)
{
    __shared__ float tl[32][33];
    const int z = blockIdx.z;
    const float* W = (z == 0) ? Wq : (z == 1) ? Wk : Wv;
    int kk = blockIdx.y * 32, nn = blockIdx.x * 32;
    int tx = threadIdx.x, ty = threadIdx.y;
    #pragma unroll
    for (int i = 0; i < 4; i++)
        tl[ty + i * 8][tx] = W[(size_t)(kk + ty + i * 8) * DOUT + nn + tx];
    __syncthreads();
    #pragma unroll
    for (int i = 0; i < 4; i++) {
        float f = tl[tx][ty + i * 8];        // = W[kk+tx][nn+ty+i*8]
        size_t row = (size_t)z * 1024 + nn + ty + i * 8;
        g_Wth[row * DIN + kk + tx] = __float2half(f);
    }
}

// V [b][j][d] -> Vt [b][d][j], single fp16 (B side)
__global__ void vtrans_kernel()
{
    __shared__ float tl[32][33];
    const int bz = blockIdx.z;
    int jj = blockIdx.x * 32, dd = blockIdx.y * 32;
    int tx = threadIdx.x, ty = threadIdx.y;
    #pragma unroll
    for (int i = 0; i < 4; i++)
        tl[ty + i * 8][tx] = g_V[((size_t)bz * SEQ + jj + ty + i * 8) * DOUT + dd + tx];
    __syncthreads();
    #pragma unroll
    for (int i = 0; i < 4; i++) {
        float f = tl[tx][ty + i * 8];        // = V[jj+tx][dd+ty+i*8]
        size_t row = (size_t)bz * DOUT + dd + ty + i * 8;
        g_Vth[row * SEQ + jj + tx] = __float2half(f);
    }
}

// ---------------------------------------------------------------------------
// Softmax + P split; writes only the causally live region (j < row_end)
// ---------------------------------------------------------------------------
__device__ __forceinline__ float wr_max(float v) {
    #pragma unroll
    for (int o = 16; o > 0; o >>= 1) v = fmaxf(v, __shfl_xor_sync(0xFFFFFFFFu, v, o));
    return v;
}
__device__ __forceinline__ float wr_sum(float v) {
    #pragma unroll
    for (int o = 16; o > 0; o >>= 1) v += __shfl_xor_sync(0xFFFFFFFFu, v, o);
    return v;
}

__global__ __launch_bounds__(256) void softmax_split_kernel()
{
    const size_t row = blockIdx.x;          // b*SEQ + i
    const int i_in_b = (int)(row & (SEQ - 1));
    const int row_end = ((i_in_b >> 7) + 1) << 7;   // written (tile) region
    const float* Srow = g_S + row * SEQ;
    const int t = threadIdx.x;
    __shared__ float red[8];

    float vals[8];
    float mx = -INFINITY;
    #pragma unroll
    for (int l = 0; l < 8; l++) {
        int j = t + l * 256;
        vals[l] = (j < row_end) ? Srow[j] : -INFINITY;
        mx = fmaxf(mx, vals[l]);
    }
    mx = wr_max(mx);
    if ((t & 31) == 0) red[t >> 5] = mx;
    __syncthreads();
    if (t < 8) {
        float v = red[t];
        #pragma unroll
        for (int o = 4; o > 0; o >>= 1) v = fmaxf(v, __shfl_xor_sync(0xFFu, v, o));
        red[t] = v;
    }
    __syncthreads();
    mx = red[0];

    float sum = 0.f;
    #pragma unroll
    for (int l = 0; l < 8; l++) {
        float e = (vals[l] == -INFINITY) ? 0.f : __expf(vals[l] - mx);
        vals[l] = e;
        sum += e;
    }
    sum = wr_sum(sum);
    __syncthreads();
    if ((t & 31) == 0) red[t >> 5] = sum;
    __syncthreads();
    if (t < 8) {
        float v = red[t];
        #pragma unroll
        for (int o = 4; o > 0; o >>= 1) v += __shfl_xor_sync(0xFFu, v, o);
        red[t] = v;
    }
    __syncthreads();
    const float inv = 1.f / red[0];

    #pragma unroll
    for (int l = 0; l < 8; l++) {
        int j = t + l * 256;
        if (j < row_end) {
            float p = vals[l] * inv;
            __half h, lo; split2h(p, h, lo);
            g_Ph[row * SEQ + j] = h;
            g_Pl[row * SEQ + j] = lo;
        }
    }
}

// ---------------------------------------------------------------------------
extern "C" void kernel_launch(void* const* d_in, const int* in_sizes, int n_in,
                              void* d_out, int out_size)
{
    const float* x  = (const float*)d_in[0];
    const float* Wq = (const float*)d_in[1];
    const float* bq = (const float*)d_in[2];
    const float* Wk = (const float*)d_in[3];
    const float* bk = (const float*)d_in[4];
    const float* Wv = (const float*)d_in[5];
    const float* bv = (const float*)d_in[6];
    float* out = (float*)d_out;

    cudaFuncSetAttribute(gemm_kernel<0>, cudaFuncAttributeMaxDynamicSharedMemorySize, SMEM_SZ);
    cudaFuncSetAttribute(gemm_kernel<1>, cudaFuncAttributeMaxDynamicSharedMemorySize, SMEM_SZ);
    cudaFuncSetAttribute(gemm_kernel<2>, cudaFuncAttributeMaxDynamicSharedMemorySize, SMEM_SZ);

    prep_x_kernel<<<MTOT * DIN / 1024, 256>>>(x);
    prep_bias_kernel<<<NCAT / 256, 256>>>(bq, bk, bv);
    prep_wt_kernel<<<dim3(DOUT / 32, DIN / 32, 3), dim3(32, 8)>>>(Wq, Wk, Wv);

    // QKV: N = 3072 concat, M = 8192
    gemm_kernel<0><<<dim3(NCAT / 128, MTOT / 128), NTHREADS, SMEM_SZ>>>(out);

    vtrans_kernel<<<dim3(SEQ / 32, DOUT / 32, BATCH), dim3(32, 8)>>>();

    // Scores: lower-triangular tiles only (16*17/2 = 136 per batch)
    gemm_kernel<1><<<dim3(136, BATCH), NTHREADS, SMEM_SZ>>>(out);

    softmax_split_kernel<<<BATCH * SEQ, 256>>>();

    // PV: K truncated by causality inside kernel
    gemm_kernel<2><<<dim3(DOUT / 128, SEQ / 128, BATCH), NTHREADS, SMEM_SZ>>>(out);
}